// round 2
// baseline (speedup 1.0000x reference)
#include <cuda_runtime.h>
#include <cstdint>
#include <cstddef>

#define TT    512
#define BB    2
#define CC    256
#define TPR   12
#define HID   32
#define INNER 256
#define NQKV  768
#define BN_EPS 1e-5f
#define SCALE  0.0625f

typedef unsigned long long u64;

// ---------------- scratch (no allocs allowed) ----------------
__device__ float g_w1f[TPR * HID];
__device__ float g_b1f[HID];
__device__ float g_w2f[HID * CC];
__device__ float g_b2f[CC];
__device__ float g_xb[BB * TT * CC];       // 1 MB
__device__ float g_qkv[BB * TT * NQKV];    // 3 MB
__device__ float g_probs[BB * TT * TT];    // 2 MB

// ---------------- f32x2 helpers (sm_103a packed fp32) ----------------
__device__ __forceinline__ u64 pk2(float x, float y) {
    u64 r; asm("mov.b64 %0, {%1,%2};" : "=l"(r) : "f"(x), "f"(y)); return r;
}
__device__ __forceinline__ void upk2(u64 v, float &x, float &y) {
    asm("mov.b64 {%0,%1}, %2;" : "=f"(x), "=f"(y) : "l"(v));
}
__device__ __forceinline__ u64 fma2(u64 a, u64 b, u64 c) {
    u64 d; asm("fma.rn.f32x2 %0, %1, %2, %3;" : "=l"(d) : "l"(a), "l"(b), "l"(c)); return d;
}

// ---------------- BN fold ----------------
__global__ void fold_kernel(const float* __restrict__ w1, const float* __restrict__ b1,
                            const float* __restrict__ g1, const float* __restrict__ be1,
                            const float* __restrict__ m1, const float* __restrict__ v1,
                            const float* __restrict__ w2, const float* __restrict__ b2,
                            const float* __restrict__ g2, const float* __restrict__ be2,
                            const float* __restrict__ m2, const float* __restrict__ v2)
{
    int t = threadIdx.x;
    if (t < HID) {
        float a = g1[t] * rsqrtf(v1[t] + BN_EPS);
        g_b1f[t] = (b1[t] - m1[t]) * a + be1[t];
        for (int d = 0; d < TPR; d++) g_w1f[d * HID + t] = w1[d * HID + t] * a;
    }
    if (t < CC) {
        float a = g2[t] * rsqrtf(v2[t] + BN_EPS);
        g_b2f[t] = (b2[t] - m2[t]) * a + be2[t];
        for (int k = 0; k < HID; k++) g_w2f[k * CC + t] = w2[k * CC + t] * a;
    }
}

// ---------------- TPR-MLP + max_j + x add  (dominant kernel) ----------------
#define TJ    64
#define H1PAD 68   // row pad: 16B-aligned (272B) + low store conflicts

__global__ __launch_bounds__(256, 2) void bias_kernel(const float* __restrict__ x,
                                                      const float* __restrict__ r)
{
    __shared__ float sh_r[TT * TPR];          // 24 KB : full r[b,i,:,:] slice
    __shared__ float sh_h1[HID * H1PAD];      // 8.5 KB: h1 transposed [k][j]

    int tid = threadIdx.x;
    int bi  = blockIdx.x;                     // b*T + i

    // load r slice (contiguous 6144 floats)
    const float4* rp   = (const float4*)(r + (size_t)bi * (TT * TPR));
    float4*       shr4 = (float4*)sh_r;
    #pragma unroll
    for (int t = tid; t < TT * TPR / 4; t += 256) shr4[t] = rp[t];

    // layer-1 weights: thread's k = tid&31
    int k = tid & 31, jg = tid >> 5;
    float w1r[TPR], b1r;
    #pragma unroll
    for (int d = 0; d < TPR; d++) w1r[d] = g_w1f[d * HID + k];
    b1r = g_b1f[k];

    // layer-2 weights for this thread's column c, pre-packed (w,w)
    int c = tid;
    u64 wp[HID];
    #pragma unroll
    for (int kk = 0; kk < HID; kk++) { float w = g_w2f[kk * CC + c]; wp[kk] = pk2(w, w); }

    uint32_t h1base;
    asm("{ .reg .u64 t0; cvta.to.shared.u64 t0, %1; cvt.u32.u64 %0, t0; }"
        : "=r"(h1base) : "l"(sh_h1));

    float maxz = -3.4e38f;

    for (int tile = 0; tile < TT / TJ; tile++) {
        __syncthreads();   // sh_r ready (iter 0) / previous tile's h1 consumed
        // layer 1: 8 h1 values per thread, stored transposed [k][j]
        #pragma unroll
        for (int n = 0; n < 8; n++) {
            int jl = jg * 8 + n;
            const float* rr = &sh_r[(tile * TJ + jl) * TPR];
            float4 ra = *(const float4*)(rr);
            float4 rb = *(const float4*)(rr + 4);
            float4 rc = *(const float4*)(rr + 8);
            float h = b1r;
            h = fmaf(ra.x, w1r[0],  h); h = fmaf(ra.y, w1r[1],  h);
            h = fmaf(ra.z, w1r[2],  h); h = fmaf(ra.w, w1r[3],  h);
            h = fmaf(rb.x, w1r[4],  h); h = fmaf(rb.y, w1r[5],  h);
            h = fmaf(rb.z, w1r[6],  h); h = fmaf(rb.w, w1r[7],  h);
            h = fmaf(rc.x, w1r[8],  h); h = fmaf(rc.y, w1r[9],  h);
            h = fmaf(rc.z, w1r[10], h); h = fmaf(rc.w, w1r[11], h);
            sh_h1[k * H1PAD + jl] = fmaxf(h, 0.f);
        }
        __syncthreads();
        // layer 2: 4 j's per pass via packed f32x2 FMAs (broadcast LDS)
        for (int jp = 0; jp < TJ; jp += 4) {
            u64 acc01 = 0ull, acc23 = 0ull;
            #pragma unroll
            for (int kk = 0; kk < HID; kk++) {
                u64 h01, h23;
                asm("ld.shared.v2.b64 {%0,%1},[%2];"
                    : "=l"(h01), "=l"(h23)
                    : "r"(h1base + (uint32_t)((kk * H1PAD + jp) * 4)));
                acc01 = fma2(h01, wp[kk], acc01);
                acc23 = fma2(h23, wp[kk], acc23);
            }
            float z0, z1, z2, z3;
            upk2(acc01, z0, z1); upk2(acc23, z2, z3);
            maxz = fmaxf(maxz, fmaxf(fmaxf(z0, z1), fmaxf(z2, z3)));
        }
    }

    float bias = fmaxf(maxz + g_b2f[c], 0.f);
    g_xb[(size_t)bi * CC + c] = x[(size_t)bi * CC + c] + bias;
}

// ---------------- qkv = xb @ w_qkv  (M=1024, N=768, K=256) ----------------
__global__ __launch_bounds__(256) void qkv_kernel(const float* __restrict__ wqkv)
{
    __shared__ float As[64 * 17];
    __shared__ float Bs[16 * 68];
    int tid = threadIdx.x;
    int tx = tid & 15, ty = tid >> 4;
    int m0 = blockIdx.y * 64, n0 = blockIdx.x * 64;

    float acc[4][4] = {};

    for (int kt = 0; kt < CC; kt += 16) {
        __syncthreads();
        {   // A tile: 64 rows x 16 k
            int row = tid >> 2, kc = tid & 3;
            float4 v = *(const float4*)&g_xb[(size_t)(m0 + row) * CC + kt + kc * 4];
            As[row * 17 + kc * 4 + 0] = v.x; As[row * 17 + kc * 4 + 1] = v.y;
            As[row * 17 + kc * 4 + 2] = v.z; As[row * 17 + kc * 4 + 3] = v.w;
        }
        {   // B tile: 16 k x 64 n
            int rr = tid >> 4, cc2 = tid & 15;
            float4 v = *(const float4*)&wqkv[(size_t)(kt + rr) * NQKV + n0 + cc2 * 4];
            *(float4*)&Bs[rr * 68 + cc2 * 4] = v;
        }
        __syncthreads();
        #pragma unroll
        for (int kk = 0; kk < 16; kk++) {
            float a0 = As[(ty * 4 + 0) * 17 + kk];
            float a1 = As[(ty * 4 + 1) * 17 + kk];
            float a2 = As[(ty * 4 + 2) * 17 + kk];
            float a3 = As[(ty * 4 + 3) * 17 + kk];
            float4 bv = *(const float4*)&Bs[kk * 68 + tx * 4];
            acc[0][0] = fmaf(a0, bv.x, acc[0][0]); acc[0][1] = fmaf(a0, bv.y, acc[0][1]);
            acc[0][2] = fmaf(a0, bv.z, acc[0][2]); acc[0][3] = fmaf(a0, bv.w, acc[0][3]);
            acc[1][0] = fmaf(a1, bv.x, acc[1][0]); acc[1][1] = fmaf(a1, bv.y, acc[1][1]);
            acc[1][2] = fmaf(a1, bv.z, acc[1][2]); acc[1][3] = fmaf(a1, bv.w, acc[1][3]);
            acc[2][0] = fmaf(a2, bv.x, acc[2][0]); acc[2][1] = fmaf(a2, bv.y, acc[2][1]);
            acc[2][2] = fmaf(a2, bv.z, acc[2][2]); acc[2][3] = fmaf(a2, bv.w, acc[2][3]);
            acc[3][0] = fmaf(a3, bv.x, acc[3][0]); acc[3][1] = fmaf(a3, bv.y, acc[3][1]);
            acc[3][2] = fmaf(a3, bv.z, acc[3][2]); acc[3][3] = fmaf(a3, bv.w, acc[3][3]);
        }
    }
    #pragma unroll
    for (int m = 0; m < 4; m++) {
        float4 v = make_float4(acc[m][0], acc[m][1], acc[m][2], acc[m][3]);
        *(float4*)&g_qkv[(size_t)(m0 + ty * 4 + m) * NQKV + n0 + tx * 4] = v;
    }
}

// ---------------- dots = q@k^T * scale, softmax (per block: 8 q rows) ----------------
__global__ __launch_bounds__(256) void dots_kernel()
{
    __shared__ float qs[8 * 260];
    __shared__ float kvs[32 * 260];
    int tid = threadIdx.x;
    int b  = blockIdx.x >> 6;
    int i0 = (blockIdx.x & 63) * 8;

    // load 8 q rows
    for (int t = tid; t < 8 * 64; t += 256) {
        int row = t >> 6, c4 = t & 63;
        float4 v = *(const float4*)&g_qkv[(size_t)(b * TT + i0 + row) * NQKV + c4 * 4];
        *(float4*)&qs[row * 260 + c4 * 4] = v;
    }

    int il = tid & 7, jl = tid >> 3;
    float* prow = &g_probs[(size_t)(b * TT + i0 + il) * TT];

    for (int jt = 0; jt < 16; jt++) {
        __syncthreads();
        for (int t = tid; t < 32 * 64; t += 256) {
            int row = t >> 6, c4 = t & 63;
            float4 v = *(const float4*)&g_qkv[(size_t)(b * TT + jt * 32 + row) * NQKV + INNER + c4 * 4];
            *(float4*)&kvs[row * 260 + c4 * 4] = v;
        }
        __syncthreads();
        float s = 0.f;
        #pragma unroll 8
        for (int d = 0; d < 256; d += 4) {
            float4 qv = *(const float4*)&qs[il * 260 + d];
            float4 kv = *(const float4*)&kvs[jl * 260 + d];
            s = fmaf(qv.x, kv.x, s); s = fmaf(qv.y, kv.y, s);
            s = fmaf(qv.z, kv.z, s); s = fmaf(qv.w, kv.w, s);
        }
        prow[jt * 32 + jl] = s * SCALE;
    }

    __syncthreads();   // all dots of this block's 8 rows visible (intra-block)

    // softmax: warp w handles row i0+w
    int w = tid >> 5, ln = tid & 31;
    float* row = &g_probs[(size_t)(b * TT + i0 + w) * TT];
    float mx = -3.4e38f;
    #pragma unroll
    for (int q = 0; q < 16; q++) mx = fmaxf(mx, row[ln + q * 32]);
    #pragma unroll
    for (int o = 16; o; o >>= 1) mx = fmaxf(mx, __shfl_xor_sync(0xffffffffu, mx, o));
    float e[16], sum = 0.f;
    #pragma unroll
    for (int q = 0; q < 16; q++) { e[q] = __expf(row[ln + q * 32] - mx); sum += e[q]; }
    #pragma unroll
    for (int o = 16; o; o >>= 1) sum += __shfl_xor_sync(0xffffffffu, sum, o);
    float inv = 1.f / sum;
    #pragma unroll
    for (int q = 0; q < 16; q++) row[ln + q * 32] = e[q] * inv;
}

// ---------------- out = probs @ v ----------------
__global__ __launch_bounds__(256) void av_kernel(float* __restrict__ out)
{
    __shared__ float kvs[32 * 260];
    __shared__ float ps[8 * 33];
    int tid = threadIdx.x;
    int b  = blockIdx.x >> 6;
    int i0 = (blockIdx.x & 63) * 8;
    int il = tid & 7, g = tid >> 3;

    float a0[4] = {0.f, 0.f, 0.f, 0.f};
    float a1[4] = {0.f, 0.f, 0.f, 0.f};

    for (int jt = 0; jt < 16; jt++) {
        __syncthreads();
        for (int t = tid; t < 32 * 64; t += 256) {
            int row = t >> 6, c4 = t & 63;
            float4 v = *(const float4*)&g_qkv[(size_t)(b * TT + jt * 32 + row) * NQKV + 2 * INNER + c4 * 4];
            *(float4*)&kvs[row * 260 + c4 * 4] = v;
        }
        {
            int rr = tid >> 5, jj = tid & 31;
            ps[rr * 33 + jj] = g_probs[(size_t)(b * TT + i0 + rr) * TT + jt * 32 + jj];
        }
        __syncthreads();
        #pragma unroll 8
        for (int jj = 0; jj < 32; jj++) {
            float p = ps[il * 33 + jj];
            float4 v0 = *(const float4*)&kvs[jj * 260 + g * 4];
            float4 v1 = *(const float4*)&kvs[jj * 260 + 128 + g * 4];
            a0[0] = fmaf(p, v0.x, a0[0]); a0[1] = fmaf(p, v0.y, a0[1]);
            a0[2] = fmaf(p, v0.z, a0[2]); a0[3] = fmaf(p, v0.w, a0[3]);
            a1[0] = fmaf(p, v1.x, a1[0]); a1[1] = fmaf(p, v1.y, a1[1]);
            a1[2] = fmaf(p, v1.z, a1[2]); a1[3] = fmaf(p, v1.w, a1[3]);
        }
    }
    float* op = out + (size_t)(b * TT + i0 + il) * CC;
    *(float4*)&op[g * 4]       = make_float4(a0[0], a0[1], a0[2], a0[3]);
    *(float4*)&op[128 + g * 4] = make_float4(a1[0], a1[1], a1[2], a1[3]);
}

// ---------------- launch ----------------
extern "C" void kernel_launch(void* const* d_in, const int* in_sizes, int n_in,
                              void* d_out, int out_size)
{
    (void)in_sizes; (void)n_in; (void)out_size;
    const float* x    = (const float*)d_in[0];
    const float* r    = (const float*)d_in[1];
    const float* w1   = (const float*)d_in[2];
    const float* b1   = (const float*)d_in[3];
    const float* g1   = (const float*)d_in[4];
    const float* be1  = (const float*)d_in[5];
    const float* m1   = (const float*)d_in[6];
    const float* v1   = (const float*)d_in[7];
    const float* w2   = (const float*)d_in[8];
    const float* b2   = (const float*)d_in[9];
    const float* g2   = (const float*)d_in[10];
    const float* be2  = (const float*)d_in[11];
    const float* m2   = (const float*)d_in[12];
    const float* v2   = (const float*)d_in[13];
    const float* wqkv = (const float*)d_in[14];
    float* out = (float*)d_out;

    fold_kernel<<<1, 256>>>(w1, b1, g1, be1, m1, v1, w2, b2, g2, be2, m2, v2);
    bias_kernel<<<BB * TT, 256>>>(x, r);
    qkv_kernel<<<dim3(NQKV / 64, (BB * TT) / 64), 256>>>(wqkv);
    dots_kernel<<<128, 256>>>();
    av_kernel<<<128, 256>>>(out);
}

// round 4
// speedup vs baseline: 1.9550x; 1.9550x over previous
#include <cuda_runtime.h>
#include <cuda_bf16.h>
#include <cstdint>
#include <cstddef>

typedef unsigned long long u64;
typedef unsigned int u32;

#define TT    512
#define BB    2
#define CC    256
#define TPR   12
#define HID   32
#define INNER 256
#define NQKV  768
#define BN_EPS 1e-5f
#define SCALE  0.0625f

// ---------------- scratch (no allocs allowed) ----------------
__device__ __align__(16) u64   g_w1p[16 * TPR];   // (k even, k odd) fp32 pairs per [kp][d]
__device__ __align__(16) u64   g_b1p[16];
__device__ __align__(16) u32   g_w2ph[16 * CC];   // hi bf16x2 {k=2kp (lo), 2kp+1 (hi)} per [kp][c]
__device__ __align__(16) u32   g_w2pl[16 * CC];   // lo residual bf16x2
__device__ __align__(16) float g_b2f[CC];
__device__ __align__(16) float g_xb[BB * TT * CC];
__device__ __align__(16) float g_qkv[BB * TT * NQKV];
__device__ __align__(16) float g_probs[BB * TT * TT];

// ---------------- f32x2 / bf16 helpers ----------------
__device__ __forceinline__ u64 pk2(float x, float y) {
    u64 r; asm("mov.b64 %0, {%1,%2};" : "=l"(r) : "f"(x), "f"(y)); return r;
}
__device__ __forceinline__ void upk2(u64 v, float &x, float &y) {
    asm("mov.b64 {%0,%1}, %2;" : "=f"(x), "=f"(y) : "l"(v));
}
__device__ __forceinline__ u64 fma2(u64 a, u64 b, u64 c) {
    u64 d; asm("fma.rn.f32x2 %0, %1, %2, %3;" : "=l"(d) : "l"(a), "l"(b), "l"(c)); return d;
}
// packs: hi arg -> bits[31:16], lo arg -> bits[15:0]
__device__ __forceinline__ u32 cvt2bf(float hi, float lo) {
    u32 r; asm("cvt.rn.bf16x2.f32 %0, %1, %2;" : "=r"(r) : "f"(hi), "f"(lo)); return r;
}
__device__ __forceinline__ float bf_lo_f(u32 w) { return __int_as_float(w << 16); }
__device__ __forceinline__ float bf_hi_f(u32 w) { return __int_as_float(w & 0xffff0000u); }

__device__ __forceinline__ void mma16816(float &d0, float &d1, float &d2, float &d3,
                                         u32 a0, u32 a1, u32 a2, u32 a3,
                                         u32 b0, u32 b1) {
    asm volatile("mma.sync.aligned.m16n8k16.row.col.f32.bf16.bf16.f32 "
                 "{%0,%1,%2,%3}, {%4,%5,%6,%7}, {%8,%9}, {%0,%1,%2,%3};"
                 : "+f"(d0), "+f"(d1), "+f"(d2), "+f"(d3)
                 : "r"(a0), "r"(a1), "r"(a2), "r"(a3), "r"(b0), "r"(b1));
}

// ---------------- BN fold + weight packing ----------------
__global__ void fold_kernel(const float* __restrict__ w1, const float* __restrict__ b1,
                            const float* __restrict__ g1, const float* __restrict__ be1,
                            const float* __restrict__ m1, const float* __restrict__ v1,
                            const float* __restrict__ w2, const float* __restrict__ b2,
                            const float* __restrict__ g2, const float* __restrict__ be2,
                            const float* __restrict__ m2, const float* __restrict__ v2)
{
    __shared__ float a1s[HID], b1s[HID];
    int t = threadIdx.x;
    if (t < HID) {
        float a = g1[t] * rsqrtf(v1[t] + BN_EPS);
        a1s[t] = a;
        b1s[t] = (b1[t] - m1[t]) * a + be1[t];
    }
    __syncthreads();
    if (t < 16) {
        for (int d = 0; d < TPR; d++)
            g_w1p[t * TPR + d] = pk2(w1[d * HID + 2 * t]     * a1s[2 * t],
                                     w1[d * HID + 2 * t + 1] * a1s[2 * t + 1]);
        g_b1p[t] = pk2(b1s[2 * t], b1s[2 * t + 1]);
    }
    int c = t;
    float a2 = g2[c] * rsqrtf(v2[c] + BN_EPS);
    g_b2f[c] = (b2[c] - m2[c]) * a2 + be2[c];
    for (int kp = 0; kp < 16; kp++) {
        float w0  = w2[(2 * kp)     * CC + c] * a2;   // k even -> low half
        float w1v = w2[(2 * kp + 1) * CC + c] * a2;   // k odd  -> high half
        u32 hw = cvt2bf(w1v, w0);
        float l0 = w0  - bf_lo_f(hw);
        float l1 = w1v - bf_hi_f(hw);
        g_w2ph[kp * CC + c] = hw;
        g_w2pl[kp * CC + c] = cvt2bf(l1, l0);
    }
}

// ---------------- TPR-MLP via mma.sync bf16 (dominant kernel) ----------------
// One CTA = one (b,i). z[j][c] = sum_k h1[j][k]*w2f[k][c]; bias[c]=relu(max_j z + b2f).
// h1 stored hi|lo bf16 in SMEM rows of 144B (conflict-free A-frag LDS).
#define H1STRIDE 144

__global__ __launch_bounds__(256, 2) void bias_kernel(const float* __restrict__ x,
                                                      const float* __restrict__ r)
{
    __shared__ __align__(16) char sh_h1[256 * H1STRIDE];   // 36 KB
    __shared__ __align__(16) u64  w1s[16 * TPR + 16];

    int tid  = threadIdx.x;
    int bi   = blockIdx.x;
    int warp = tid >> 5, lane = tid & 31;
    int gid  = lane >> 2, tig = lane & 3;

    if (tid < 16 * TPR + 16)
        w1s[tid] = (tid < 16 * TPR) ? g_w1p[tid] : g_b1p[tid - 16 * TPR];

    // preload B fragments for this warp's 32 columns: c = warp*32 + nt*8 + gid
    u32 bh[4][2][2], bl[4][2][2];
    #pragma unroll
    for (int nt = 0; nt < 4; nt++) {
        int c = warp * 32 + nt * 8 + gid;
        #pragma unroll
        for (int ks = 0; ks < 2; ks++) {
            bh[nt][ks][0] = g_w2ph[(ks * 8 + tig)     * CC + c];
            bh[nt][ks][1] = g_w2ph[(ks * 8 + tig + 4) * CC + c];
            bl[nt][ks][0] = g_w2pl[(ks * 8 + tig)     * CC + c];
            bl[nt][ks][1] = g_w2pl[(ks * 8 + tig + 4) * CC + c];
        }
    }

    float m0[4], m1[4];
    #pragma unroll
    for (int nt = 0; nt < 4; nt++) { m0[nt] = -3.4e38f; m1[nt] = -3.4e38f; }

    __syncthreads();

    for (int chunk = 0; chunk < 2; chunk++) {
        // ---- layer 1: this thread computes h1 row j = chunk*256+tid ----
        {
            int j = chunk * 256 + tid;
            const float4* rrow = (const float4*)(r + (size_t)bi * (TT * TPR) + (size_t)j * TPR);
            float4 ra = rrow[0], rb = rrow[1], rc = rrow[2];
            u64 r2[12];
            r2[0]  = pk2(ra.x, ra.x); r2[1]  = pk2(ra.y, ra.y);
            r2[2]  = pk2(ra.z, ra.z); r2[3]  = pk2(ra.w, ra.w);
            r2[4]  = pk2(rb.x, rb.x); r2[5]  = pk2(rb.y, rb.y);
            r2[6]  = pk2(rb.z, rb.z); r2[7]  = pk2(rb.w, rb.w);
            r2[8]  = pk2(rc.x, rc.x); r2[9]  = pk2(rc.y, rc.y);
            r2[10] = pk2(rc.z, rc.z); r2[11] = pk2(rc.w, rc.w);
            u32 hw[16], lw[16];
            #pragma unroll 4
            for (int kp = 0; kp < 16; kp++) {
                u64 acc = w1s[16 * TPR + kp];
                #pragma unroll
                for (int d = 0; d < 12; d++) acc = fma2(r2[d], w1s[kp * TPR + d], acc);
                float h0, h1; upk2(acc, h0, h1);
                h0 = fmaxf(h0, 0.f); h1 = fmaxf(h1, 0.f);
                u32 h = cvt2bf(h1, h0);            // low=k even, high=k odd
                float l0 = h0 - bf_lo_f(h), l1 = h1 - bf_hi_f(h);
                hw[kp] = h; lw[kp] = cvt2bf(l1, l0);
            }
            char* rowp = sh_h1 + tid * H1STRIDE;
            #pragma unroll
            for (int q = 0; q < 4; q++) {
                *(uint4*)(rowp + q * 16)      = make_uint4(hw[4*q], hw[4*q+1], hw[4*q+2], hw[4*q+3]);
                *(uint4*)(rowp + 64 + q * 16) = make_uint4(lw[4*q], lw[4*q+1], lw[4*q+2], lw[4*q+3]);
            }
        }
        __syncthreads();

        // ---- layer 2: 16 j-tiles of 16 rows; mma + running max ----
        #pragma unroll 2
        for (int jt = 0; jt < 16; jt++) {
            const char* base = sh_h1 + (jt * 16 + gid) * H1STRIDE + tig * 4;
            u32 ah0[4], ah1[4], al0[4], al1[4];
            // ks0 hi
            ah0[0] = *(const u32*)(base);
            ah0[1] = *(const u32*)(base + 8 * H1STRIDE);
            ah0[2] = *(const u32*)(base + 16);
            ah0[3] = *(const u32*)(base + 8 * H1STRIDE + 16);
            // ks1 hi
            ah1[0] = *(const u32*)(base + 32);
            ah1[1] = *(const u32*)(base + 8 * H1STRIDE + 32);
            ah1[2] = *(const u32*)(base + 48);
            ah1[3] = *(const u32*)(base + 8 * H1STRIDE + 48);
            // ks0 lo
            al0[0] = *(const u32*)(base + 64);
            al0[1] = *(const u32*)(base + 8 * H1STRIDE + 64);
            al0[2] = *(const u32*)(base + 80);
            al0[3] = *(const u32*)(base + 8 * H1STRIDE + 80);
            // ks1 lo
            al1[0] = *(const u32*)(base + 96);
            al1[1] = *(const u32*)(base + 8 * H1STRIDE + 96);
            al1[2] = *(const u32*)(base + 112);
            al1[3] = *(const u32*)(base + 8 * H1STRIDE + 112);

            #pragma unroll
            for (int nt = 0; nt < 4; nt++) {
                float d0 = 0.f, d1 = 0.f, d2 = 0.f, d3 = 0.f;
                mma16816(d0,d1,d2,d3, ah0[0],ah0[1],ah0[2],ah0[3], bh[nt][0][0], bh[nt][0][1]);
                mma16816(d0,d1,d2,d3, ah1[0],ah1[1],ah1[2],ah1[3], bh[nt][1][0], bh[nt][1][1]);
                mma16816(d0,d1,d2,d3, ah0[0],ah0[1],ah0[2],ah0[3], bl[nt][0][0], bl[nt][0][1]);
                mma16816(d0,d1,d2,d3, ah1[0],ah1[1],ah1[2],ah1[3], bl[nt][1][0], bl[nt][1][1]);
                mma16816(d0,d1,d2,d3, al0[0],al0[1],al0[2],al0[3], bh[nt][0][0], bh[nt][0][1]);
                mma16816(d0,d1,d2,d3, al1[0],al1[1],al1[2],al1[3], bh[nt][1][0], bh[nt][1][1]);
                m0[nt] = fmaxf(m0[nt], fmaxf(d0, d2));
                m1[nt] = fmaxf(m1[nt], fmaxf(d1, d3));
            }
        }
        __syncthreads();
    }

    // reduce max across groupID (lanes sharing tig), then write
    #pragma unroll
    for (int nt = 0; nt < 4; nt++) {
        #pragma unroll
        for (int o = 4; o < 32; o <<= 1) {
            m0[nt] = fmaxf(m0[nt], __shfl_xor_sync(0xffffffffu, m0[nt], o));
            m1[nt] = fmaxf(m1[nt], __shfl_xor_sync(0xffffffffu, m1[nt], o));
        }
        if (gid == 0) {
            int c0 = warp * 32 + nt * 8 + tig * 2;
            float b0v = fmaxf(m0[nt] + g_b2f[c0],     0.f);
            float b1v = fmaxf(m1[nt] + g_b2f[c0 + 1], 0.f);
            size_t o0 = (size_t)bi * CC + c0;
            g_xb[o0]     = x[o0]     + b0v;
            g_xb[o0 + 1] = x[o0 + 1] + b1v;
        }
    }
}

// ---------------- qkv = xb @ w_qkv  (M=1024, N=768, K=256) ----------------
__global__ __launch_bounds__(256) void qkv_kernel(const float* __restrict__ wqkv)
{
    __shared__ float As[64 * 17];
    __shared__ float Bs[16 * 68];
    int tid = threadIdx.x;
    int tx = tid & 15, ty = tid >> 4;
    int m0 = blockIdx.y * 64, n0 = blockIdx.x * 64;

    float acc[4][4] = {};

    for (int kt = 0; kt < CC; kt += 16) {
        __syncthreads();
        {
            int row = tid >> 2, kc = tid & 3;
            float4 v = *(const float4*)&g_xb[(size_t)(m0 + row) * CC + kt + kc * 4];
            As[row * 17 + kc * 4 + 0] = v.x; As[row * 17 + kc * 4 + 1] = v.y;
            As[row * 17 + kc * 4 + 2] = v.z; As[row * 17 + kc * 4 + 3] = v.w;
        }
        {
            int rr = tid >> 4, cc2 = tid & 15;
            float4 v = *(const float4*)&wqkv[(size_t)(kt + rr) * NQKV + n0 + cc2 * 4];
            *(float4*)&Bs[rr * 68 + cc2 * 4] = v;
        }
        __syncthreads();
        #pragma unroll
        for (int kk = 0; kk < 16; kk++) {
            float a0 = As[(ty * 4 + 0) * 17 + kk];
            float a1 = As[(ty * 4 + 1) * 17 + kk];
            float a2 = As[(ty * 4 + 2) * 17 + kk];
            float a3 = As[(ty * 4 + 3) * 17 + kk];
            float4 bv = *(const float4*)&Bs[kk * 68 + tx * 4];
            acc[0][0] = fmaf(a0, bv.x, acc[0][0]); acc[0][1] = fmaf(a0, bv.y, acc[0][1]);
            acc[0][2] = fmaf(a0, bv.z, acc[0][2]); acc[0][3] = fmaf(a0, bv.w, acc[0][3]);
            acc[1][0] = fmaf(a1, bv.x, acc[1][0]); acc[1][1] = fmaf(a1, bv.y, acc[1][1]);
            acc[1][2] = fmaf(a1, bv.z, acc[1][2]); acc[1][3] = fmaf(a1, bv.w, acc[1][3]);
            acc[2][0] = fmaf(a2, bv.x, acc[2][0]); acc[2][1] = fmaf(a2, bv.y, acc[2][1]);
            acc[2][2] = fmaf(a2, bv.z, acc[2][2]); acc[2][3] = fmaf(a2, bv.w, acc[2][3]);
            acc[3][0] = fmaf(a3, bv.x, acc[3][0]); acc[3][1] = fmaf(a3, bv.y, acc[3][1]);
            acc[3][2] = fmaf(a3, bv.z, acc[3][2]); acc[3][3] = fmaf(a3, bv.w, acc[3][3]);
        }
    }
    #pragma unroll
    for (int m = 0; m < 4; m++) {
        float4 v = make_float4(acc[m][0], acc[m][1], acc[m][2], acc[m][3]);
        *(float4*)&g_qkv[(size_t)(m0 + ty * 4 + m) * NQKV + n0 + tx * 4] = v;
    }
}

// ---------------- dots = q@k^T * scale + softmax ----------------
__global__ __launch_bounds__(256) void dots_kernel()
{
    __shared__ float qs[8 * 260];
    __shared__ float kvs[32 * 260];
    int tid = threadIdx.x;
    int b  = blockIdx.x >> 6;
    int i0 = (blockIdx.x & 63) * 8;

    for (int t = tid; t < 8 * 64; t += 256) {
        int row = t >> 6, c4 = t & 63;
        float4 v = *(const float4*)&g_qkv[(size_t)(b * TT + i0 + row) * NQKV + c4 * 4];
        *(float4*)&qs[row * 260 + c4 * 4] = v;
    }

    int il = tid & 7, jl = tid >> 3;
    float* prow = &g_probs[(size_t)(b * TT + i0 + il) * TT];

    for (int jt = 0; jt < 16; jt++) {
        __syncthreads();
        for (int t = tid; t < 32 * 64; t += 256) {
            int row = t >> 6, c4 = t & 63;
            float4 v = *(const float4*)&g_qkv[(size_t)(b * TT + jt * 32 + row) * NQKV + INNER + c4 * 4];
            *(float4*)&kvs[row * 260 + c4 * 4] = v;
        }
        __syncthreads();
        const ulonglong2* qp = (const ulonglong2*)&qs[il * 260];
        const ulonglong2* kk = (const ulonglong2*)&kvs[jl * 260];
        u64 a0 = 0ull, a1 = 0ull, a2 = 0ull, a3 = 0ull;
        #pragma unroll
        for (int i = 0; i < 64; i += 2) {
            ulonglong2 q0 = qp[i], k0 = kk[i];
            ulonglong2 q1 = qp[i + 1], k1 = kk[i + 1];
            a0 = fma2(q0.x, k0.x, a0); a1 = fma2(q0.y, k0.y, a1);
            a2 = fma2(q1.x, k1.x, a2); a3 = fma2(q1.y, k1.y, a3);
        }
        float s0, s1, s2, s3, s4, s5, s6, s7;
        upk2(a0, s0, s1); upk2(a1, s2, s3); upk2(a2, s4, s5); upk2(a3, s6, s7);
        prow[jt * 32 + jl] = ((s0 + s1) + (s2 + s3) + (s4 + s5) + (s6 + s7)) * SCALE;
    }

    __syncthreads();

    int w = tid >> 5, ln = tid & 31;
    float* row = &g_probs[(size_t)(b * TT + i0 + w) * TT];
    float mx = -3.4e38f;
    #pragma unroll
    for (int q = 0; q < 16; q++) mx = fmaxf(mx, row[ln + q * 32]);
    #pragma unroll
    for (int o = 16; o; o >>= 1) mx = fmaxf(mx, __shfl_xor_sync(0xffffffffu, mx, o));
    float e[16], sum = 0.f;
    #pragma unroll
    for (int q = 0; q < 16; q++) { e[q] = __expf(row[ln + q * 32] - mx); sum += e[q]; }
    #pragma unroll
    for (int o = 16; o; o >>= 1) sum += __shfl_xor_sync(0xffffffffu, sum, o);
    float inv = 1.f / sum;
    #pragma unroll
    for (int q = 0; q < 16; q++) row[ln + q * 32] = e[q] * inv;
}

// ---------------- out = probs @ v ----------------
__global__ __launch_bounds__(256) void av_kernel(float* __restrict__ out)
{
    __shared__ float kvs[32 * 260];
    __shared__ float ps[8 * 33];
    int tid = threadIdx.x;
    int b  = blockIdx.x >> 6;
    int i0 = (blockIdx.x & 63) * 8;
    int il = tid & 7, g = tid >> 3;

    u64 c0 = 0ull, c1 = 0ull, c2 = 0ull, c3 = 0ull;

    for (int jt = 0; jt < 16; jt++) {
        __syncthreads();
        for (int t = tid; t < 32 * 64; t += 256) {
            int row = t >> 6, c4 = t & 63;
            float4 v = *(const float4*)&g_qkv[(size_t)(b * TT + jt * 32 + row) * NQKV + 2 * INNER + c4 * 4];
            *(float4*)&kvs[row * 260 + c4 * 4] = v;
        }
        {
            int rr = tid >> 5, jj = tid & 31;
            ps[rr * 33 + jj] = g_probs[(size_t)(b * TT + i0 + rr) * TT + jt * 32 + jj];
        }
        __syncthreads();
        #pragma unroll 8
        for (int jj = 0; jj < 32; jj++) {
            u64 p2 = pk2(ps[il * 33 + jj], ps[il * 33 + jj]);
            ulonglong2 v0 = *(const ulonglong2*)&kvs[jj * 260 + g * 4];
            ulonglong2 v1 = *(const ulonglong2*)&kvs[jj * 260 + 128 + g * 4];
            c0 = fma2(p2, v0.x, c0); c1 = fma2(p2, v0.y, c1);
            c2 = fma2(p2, v1.x, c2); c3 = fma2(p2, v1.y, c3);
        }
    }
    float* op = out + (size_t)(b * TT + i0 + il) * CC;
    float x0, x1, x2, x3;
    upk2(c0, x0, x1); upk2(c1, x2, x3);
    *(float4*)&op[g * 4] = make_float4(x0, x1, x2, x3);
    upk2(c2, x0, x1); upk2(c3, x2, x3);
    *(float4*)&op[128 + g * 4] = make_float4(x0, x1, x2, x3);
}

// ---------------- launch ----------------
extern "C" void kernel_launch(void* const* d_in, const int* in_sizes, int n_in,
                              void* d_out, int out_size)
{
    (void)in_sizes; (void)n_in; (void)out_size;
    const float* x    = (const float*)d_in[0];
    const float* r    = (const float*)d_in[1];
    const float* w1   = (const float*)d_in[2];
    const float* b1   = (const float*)d_in[3];
    const float* g1   = (const float*)d_in[4];
    const float* be1  = (const float*)d_in[5];
    const float* m1   = (const float*)d_in[6];
    const float* v1   = (const float*)d_in[7];
    const float* w2   = (const float*)d_in[8];
    const float* b2   = (const float*)d_in[9];
    const float* g2   = (const float*)d_in[10];
    const float* be2  = (const float*)d_in[11];
    const float* m2   = (const float*)d_in[12];
    const float* v2   = (const float*)d_in[13];
    const float* wqkv = (const float*)d_in[14];
    float* out = (float*)d_out;

    fold_kernel<<<1, 256>>>(w1, b1, g1, be1, m1, v1, w2, b2, g2, be2, m2, v2);
    bias_kernel<<<BB * TT, 256>>>(x, r);
    qkv_kernel<<<dim3(NQKV / 64, (BB * TT) / 64), 256>>>(wqkv);
    dots_kernel<<<128, 256>>>();
    av_kernel<<<128, 256>>>(out);
}

// round 6
// speedup vs baseline: 3.1769x; 1.6250x over previous
#include <cuda_runtime.h>
#include <cuda_bf16.h>
#include <cstdint>
#include <cstddef>

typedef unsigned long long u64;
typedef unsigned int u32;

#define TT    512
#define BB    2
#define CC    256
#define TPR   12
#define HID   32
#define INNER 256
#define NQKV  768
#define BN_EPS 1e-5f
#define SCALE  0.0625f

// ---------------- scratch (no allocs allowed) ----------------
__device__ __align__(16) u64   g_w1p[16 * TPR];
__device__ __align__(16) u64   g_b1p[16];
__device__ __align__(16) u32   g_w2ph[16 * CC];
__device__ __align__(16) u32   g_w2pl[16 * CC];
__device__ __align__(16) float g_b2f[CC];
__device__ __align__(16) float g_xb[BB * TT * CC];
__device__ __align__(16) float g_qkv[BB * TT * NQKV];
// fragment-native bf16 hi/lo packs:
// g_q2/g_k2: [row(1024)][ks(16)][tig(4)][{h(p), h(p+4), l(p), l(p+4)}]  (p = ks*8+tig, d = 2p,2p+1)
__device__ __align__(16) u32   g_q2[BB * TT * 256];
__device__ __align__(16) u32   g_k2[BB * TT * 256];
// g_vt2: [b][ks(32)][d(256)][tig(4)][{vh(jloc 2tig,2tig+1), vh(2tig+8,+9), vl, vl}]
__device__ __align__(16) u32   g_vt2[BB * 32 * 256 * 16];

// ---------------- helpers ----------------
__device__ __forceinline__ u64 pk2(float x, float y) {
    u64 r; asm("mov.b64 %0, {%1,%2};" : "=l"(r) : "f"(x), "f"(y)); return r;
}
__device__ __forceinline__ void upk2(u64 v, float &x, float &y) {
    asm("mov.b64 {%0,%1}, %2;" : "=f"(x), "=f"(y) : "l"(v));
}
__device__ __forceinline__ u64 fma2(u64 a, u64 b, u64 c) {
    u64 d; asm("fma.rn.f32x2 %0, %1, %2, %3;" : "=l"(d) : "l"(a), "l"(b), "l"(c)); return d;
}
__device__ __forceinline__ u32 cvt2bf(float hi, float lo) {
    u32 r; asm("cvt.rn.bf16x2.f32 %0, %1, %2;" : "=r"(r) : "f"(hi), "f"(lo)); return r;
}
__device__ __forceinline__ float bf_lo_f(u32 w) { return __int_as_float(w << 16); }
__device__ __forceinline__ float bf_hi_f(u32 w) { return __int_as_float(w & 0xffff0000u); }

__device__ __forceinline__ void mma16816(float &d0, float &d1, float &d2, float &d3,
                                         u32 a0, u32 a1, u32 a2, u32 a3,
                                         u32 b0, u32 b1) {
    asm volatile("mma.sync.aligned.m16n8k16.row.col.f32.bf16.bf16.f32 "
                 "{%0,%1,%2,%3}, {%4,%5,%6,%7}, {%8,%9}, {%0,%1,%2,%3};"
                 : "+f"(d0), "+f"(d1), "+f"(d2), "+f"(d3)
                 : "r"(a0), "r"(a1), "r"(a2), "r"(a3), "r"(b0), "r"(b1));
}

// ---------------- BN fold + weight packing ----------------
__global__ void fold_kernel(const float* __restrict__ w1, const float* __restrict__ b1,
                            const float* __restrict__ g1, const float* __restrict__ be1,
                            const float* __restrict__ m1, const float* __restrict__ v1,
                            const float* __restrict__ w2, const float* __restrict__ b2,
                            const float* __restrict__ g2, const float* __restrict__ be2,
                            const float* __restrict__ m2, const float* __restrict__ v2)
{
    __shared__ float a1s[HID], b1s[HID];
    int t = threadIdx.x;
    if (t < HID) {
        float a = g1[t] * rsqrtf(v1[t] + BN_EPS);
        a1s[t] = a;
        b1s[t] = (b1[t] - m1[t]) * a + be1[t];
    }
    __syncthreads();
    if (t < 16) {
        for (int d = 0; d < TPR; d++)
            g_w1p[t * TPR + d] = pk2(w1[d * HID + 2 * t]     * a1s[2 * t],
                                     w1[d * HID + 2 * t + 1] * a1s[2 * t + 1]);
        g_b1p[t] = pk2(b1s[2 * t], b1s[2 * t + 1]);
    }
    int c = t;
    float a2 = g2[c] * rsqrtf(v2[c] + BN_EPS);
    g_b2f[c] = (b2[c] - m2[c]) * a2 + be2[c];
    for (int kp = 0; kp < 16; kp++) {
        float w0  = w2[(2 * kp)     * CC + c] * a2;
        float w1v = w2[(2 * kp + 1) * CC + c] * a2;
        u32 hw = cvt2bf(w1v, w0);
        float l0 = w0  - bf_lo_f(hw);
        float l1 = w1v - bf_hi_f(hw);
        g_w2ph[kp * CC + c] = hw;
        g_w2pl[kp * CC + c] = cvt2bf(l1, l0);
    }
}

// ---------------- TPR-MLP via mma.sync bf16 ----------------
#define H1STRIDE 144

__global__ __launch_bounds__(256, 2) void bias_kernel(const float* __restrict__ x,
                                                      const float* __restrict__ r)
{
    __shared__ __align__(16) char sh_h1[256 * H1STRIDE];
    __shared__ __align__(16) u64  w1s[16 * TPR + 16];

    int tid  = threadIdx.x;
    int bi   = blockIdx.x;
    int warp = tid >> 5, lane = tid & 31;
    int gid  = lane >> 2, tig = lane & 3;

    if (tid < 16 * TPR + 16)
        w1s[tid] = (tid < 16 * TPR) ? g_w1p[tid] : g_b1p[tid - 16 * TPR];

    u32 bh[4][2][2], bl[4][2][2];
    #pragma unroll
    for (int nt = 0; nt < 4; nt++) {
        int c = warp * 32 + nt * 8 + gid;
        #pragma unroll
        for (int ks = 0; ks < 2; ks++) {
            bh[nt][ks][0] = g_w2ph[(ks * 8 + tig)     * CC + c];
            bh[nt][ks][1] = g_w2ph[(ks * 8 + tig + 4) * CC + c];
            bl[nt][ks][0] = g_w2pl[(ks * 8 + tig)     * CC + c];
            bl[nt][ks][1] = g_w2pl[(ks * 8 + tig + 4) * CC + c];
        }
    }

    float m0[4], m1[4];
    #pragma unroll
    for (int nt = 0; nt < 4; nt++) { m0[nt] = -3.4e38f; m1[nt] = -3.4e38f; }

    __syncthreads();

    for (int chunk = 0; chunk < 2; chunk++) {
        {
            int j = chunk * 256 + tid;
            const float4* rrow = (const float4*)(r + (size_t)bi * (TT * TPR) + (size_t)j * TPR);
            float4 ra = rrow[0], rb = rrow[1], rc = rrow[2];
            u64 r2[12];
            r2[0]  = pk2(ra.x, ra.x); r2[1]  = pk2(ra.y, ra.y);
            r2[2]  = pk2(ra.z, ra.z); r2[3]  = pk2(ra.w, ra.w);
            r2[4]  = pk2(rb.x, rb.x); r2[5]  = pk2(rb.y, rb.y);
            r2[6]  = pk2(rb.z, rb.z); r2[7]  = pk2(rb.w, rb.w);
            r2[8]  = pk2(rc.x, rc.x); r2[9]  = pk2(rc.y, rc.y);
            r2[10] = pk2(rc.z, rc.z); r2[11] = pk2(rc.w, rc.w);
            u32 hw[16], lw[16];
            #pragma unroll 4
            for (int kp = 0; kp < 16; kp++) {
                u64 acc = w1s[16 * TPR + kp];
                #pragma unroll
                for (int d = 0; d < 12; d++) acc = fma2(r2[d], w1s[kp * TPR + d], acc);
                float h0, h1; upk2(acc, h0, h1);
                h0 = fmaxf(h0, 0.f); h1 = fmaxf(h1, 0.f);
                u32 h = cvt2bf(h1, h0);
                float l0 = h0 - bf_lo_f(h), l1 = h1 - bf_hi_f(h);
                hw[kp] = h; lw[kp] = cvt2bf(l1, l0);
            }
            char* rowp = sh_h1 + tid * H1STRIDE;
            #pragma unroll
            for (int q = 0; q < 4; q++) {
                *(uint4*)(rowp + q * 16)      = make_uint4(hw[4*q], hw[4*q+1], hw[4*q+2], hw[4*q+3]);
                *(uint4*)(rowp + 64 + q * 16) = make_uint4(lw[4*q], lw[4*q+1], lw[4*q+2], lw[4*q+3]);
            }
        }
        __syncthreads();

        #pragma unroll 2
        for (int jt = 0; jt < 16; jt++) {
            const char* base = sh_h1 + (jt * 16 + gid) * H1STRIDE + tig * 4;
            u32 ah0[4], ah1[4], al0[4], al1[4];
            ah0[0] = *(const u32*)(base);
            ah0[1] = *(const u32*)(base + 8 * H1STRIDE);
            ah0[2] = *(const u32*)(base + 16);
            ah0[3] = *(const u32*)(base + 8 * H1STRIDE + 16);
            ah1[0] = *(const u32*)(base + 32);
            ah1[1] = *(const u32*)(base + 8 * H1STRIDE + 32);
            ah1[2] = *(const u32*)(base + 48);
            ah1[3] = *(const u32*)(base + 8 * H1STRIDE + 48);
            al0[0] = *(const u32*)(base + 64);
            al0[1] = *(const u32*)(base + 8 * H1STRIDE + 64);
            al0[2] = *(const u32*)(base + 80);
            al0[3] = *(const u32*)(base + 8 * H1STRIDE + 80);
            al1[0] = *(const u32*)(base + 96);
            al1[1] = *(const u32*)(base + 8 * H1STRIDE + 96);
            al1[2] = *(const u32*)(base + 112);
            al1[3] = *(const u32*)(base + 8 * H1STRIDE + 112);

            #pragma unroll
            for (int nt = 0; nt < 4; nt++) {
                float d0 = 0.f, d1 = 0.f, d2 = 0.f, d3 = 0.f;
                mma16816(d0,d1,d2,d3, ah0[0],ah0[1],ah0[2],ah0[3], bh[nt][0][0], bh[nt][0][1]);
                mma16816(d0,d1,d2,d3, ah1[0],ah1[1],ah1[2],ah1[3], bh[nt][1][0], bh[nt][1][1]);
                mma16816(d0,d1,d2,d3, ah0[0],ah0[1],ah0[2],ah0[3], bl[nt][0][0], bl[nt][0][1]);
                mma16816(d0,d1,d2,d3, ah1[0],ah1[1],ah1[2],ah1[3], bl[nt][1][0], bl[nt][1][1]);
                mma16816(d0,d1,d2,d3, al0[0],al0[1],al0[2],al0[3], bh[nt][0][0], bh[nt][0][1]);
                mma16816(d0,d1,d2,d3, al1[0],al1[1],al1[2],al1[3], bh[nt][1][0], bh[nt][1][1]);
                m0[nt] = fmaxf(m0[nt], fmaxf(d0, d2));
                m1[nt] = fmaxf(m1[nt], fmaxf(d1, d3));
            }
        }
        __syncthreads();
    }

    #pragma unroll
    for (int nt = 0; nt < 4; nt++) {
        #pragma unroll
        for (int o = 4; o < 32; o <<= 1) {
            m0[nt] = fmaxf(m0[nt], __shfl_xor_sync(0xffffffffu, m0[nt], o));
            m1[nt] = fmaxf(m1[nt], __shfl_xor_sync(0xffffffffu, m1[nt], o));
        }
        if (gid == 0) {
            int c0 = warp * 32 + nt * 8 + tig * 2;
            float b0v = fmaxf(m0[nt] + g_b2f[c0],     0.f);
            float b1v = fmaxf(m1[nt] + g_b2f[c0 + 1], 0.f);
            size_t o0 = (size_t)bi * CC + c0;
            g_xb[o0]     = x[o0]     + b0v;
            g_xb[o0 + 1] = x[o0 + 1] + b1v;
        }
    }
}

// ---------------- qkv = xb @ w_qkv ----------------
__global__ __launch_bounds__(256) void qkv_kernel(const float* __restrict__ wqkv)
{
    __shared__ float As[64 * 17];
    __shared__ float Bs[16 * 68];
    int tid = threadIdx.x;
    int tx = tid & 15, ty = tid >> 4;
    int m0 = blockIdx.y * 64, n0 = blockIdx.x * 64;

    float acc[4][4] = {};

    for (int kt = 0; kt < CC; kt += 16) {
        __syncthreads();
        {
            int row = tid >> 2, kc = tid & 3;
            float4 v = *(const float4*)&g_xb[(size_t)(m0 + row) * CC + kt + kc * 4];
            As[row * 17 + kc * 4 + 0] = v.x; As[row * 17 + kc * 4 + 1] = v.y;
            As[row * 17 + kc * 4 + 2] = v.z; As[row * 17 + kc * 4 + 3] = v.w;
        }
        {
            int rr = tid >> 4, cc2 = tid & 15;
            float4 v = *(const float4*)&wqkv[(size_t)(kt + rr) * NQKV + n0 + cc2 * 4];
            *(float4*)&Bs[rr * 68 + cc2 * 4] = v;
        }
        __syncthreads();
        #pragma unroll
        for (int kk = 0; kk < 16; kk++) {
            float a0 = As[(ty * 4 + 0) * 17 + kk];
            float a1 = As[(ty * 4 + 1) * 17 + kk];
            float a2 = As[(ty * 4 + 2) * 17 + kk];
            float a3 = As[(ty * 4 + 3) * 17 + kk];
            float4 bv = *(const float4*)&Bs[kk * 68 + tx * 4];
            acc[0][0] = fmaf(a0, bv.x, acc[0][0]); acc[0][1] = fmaf(a0, bv.y, acc[0][1]);
            acc[0][2] = fmaf(a0, bv.z, acc[0][2]); acc[0][3] = fmaf(a0, bv.w, acc[0][3]);
            acc[1][0] = fmaf(a1, bv.x, acc[1][0]); acc[1][1] = fmaf(a1, bv.y, acc[1][1]);
            acc[1][2] = fmaf(a1, bv.z, acc[1][2]); acc[1][3] = fmaf(a1, bv.w, acc[1][3]);
            acc[2][0] = fmaf(a2, bv.x, acc[2][0]); acc[2][1] = fmaf(a2, bv.y, acc[2][1]);
            acc[2][2] = fmaf(a2, bv.z, acc[2][2]); acc[2][3] = fmaf(a2, bv.w, acc[2][3]);
            acc[3][0] = fmaf(a3, bv.x, acc[3][0]); acc[3][1] = fmaf(a3, bv.y, acc[3][1]);
            acc[3][2] = fmaf(a3, bv.z, acc[3][2]); acc[3][3] = fmaf(a3, bv.w, acc[3][3]);
        }
    }
    #pragma unroll
    for (int m = 0; m < 4; m++) {
        float4 v = make_float4(acc[m][0], acc[m][1], acc[m][2], acc[m][3]);
        *(float4*)&g_qkv[(size_t)(m0 + ty * 4 + m) * NQKV + n0 + tx * 4] = v;
    }
}

// ---------------- convert q,k to fragment-native bf16 hi/lo ----------------
__global__ __launch_bounds__(256) void convert_qk_kernel()
{
    int tid = threadIdx.x;
    int row  = blockIdx.x * 2 + (tid >> 7);
    int half = (tid >> 6) & 1;
    int sub  = tid & 63;
    int ks = sub >> 2, tig = sub & 3;
    const float* src = g_qkv + (size_t)row * NQKV + half * 256;
    int p = ks * 8 + tig;
    float2 fa = *(const float2*)(src + 2 * p);
    float2 fb = *(const float2*)(src + 2 * p + 8);
    u32 h0 = cvt2bf(fa.y, fa.x);
    u32 h1 = cvt2bf(fb.y, fb.x);
    u32 l0 = cvt2bf(fa.y - bf_hi_f(h0), fa.x - bf_lo_f(h0));
    u32 l1 = cvt2bf(fb.y - bf_hi_f(h1), fb.x - bf_lo_f(h1));
    u32* dst = (half ? g_k2 : g_q2) + (size_t)row * 256 + sub * 4;
    *(uint4*)dst = make_uint4(h0, h1, l0, l1);
}

// ---------------- convert+transpose V: [b][ks][d][tig][4] ----------------
__global__ __launch_bounds__(256) void convert_v_kernel()
{
    __shared__ float sv[16 * 256];
    int tid = threadIdx.x;
    int b = blockIdx.x >> 5, ks = blockIdx.x & 31;
    #pragma unroll
    for (int rr = 0; rr < 16; rr++)
        sv[rr * 256 + tid] = g_qkv[(size_t)(b * TT + ks * 16 + rr) * NQKV + 2 * 256 + tid];
    __syncthreads();
    int d = tid;
    u32* dst = g_vt2 + ((size_t)(b * 32 + ks) * 256 + d) * 16;
    #pragma unroll
    for (int tig = 0; tig < 4; tig++) {
        float e0 = sv[(2 * tig)     * 256 + d], o0 = sv[(2 * tig + 1) * 256 + d];
        float e1 = sv[(2 * tig + 8) * 256 + d], o1 = sv[(2 * tig + 9) * 256 + d];
        u32 h0 = cvt2bf(o0, e0), h1 = cvt2bf(o1, e1);
        u32 l0 = cvt2bf(o0 - bf_hi_f(h0), e0 - bf_lo_f(h0));
        u32 l1 = cvt2bf(o1 - bf_hi_f(h1), e1 - bf_lo_f(h1));
        *(uint4*)(dst + tig * 4) = make_uint4(h0, h1, l0, l1);
    }
}

// ---------------- fused attention: S=QK^T, softmax, O=PV ----------------
#define QSTR 260
#define SSTR 520
#define PSTR 260
#define ATT_SMEM (16*QSTR*4 + 16*SSTR*4 + 2*16*PSTR*4)

__global__ __launch_bounds__(256, 1) void attn_kernel(float* __restrict__ out)
{
    extern __shared__ char smem[];
    u32*   sq  = (u32*)smem;                                   // [16][260]
    float* ssc = (float*)(smem + 16 * QSTR * 4);               // [16][520]
    u32*   sph = (u32*)(smem + 16 * QSTR * 4 + 16 * SSTR * 4); // [16][260]
    u32*   spl = sph + 16 * PSTR;

    int tid = threadIdx.x;
    int w = tid >> 5, lane = tid & 31, gid = lane >> 2, tig = lane & 3;
    int b  = blockIdx.x >> 5;
    int i0 = (blockIdx.x & 31) * 16;

    // stage Q tile (16 rows x 1KB)
    {
        int i = tid >> 4, c0 = (tid & 15) * 16;
        const uint4* src = (const uint4*)(g_q2 + (size_t)(b * TT + i0 + i) * 256 + c0);
        uint4* dst = (uint4*)(sq + i * QSTR + c0);
        dst[0] = src[0]; dst[1] = src[1]; dst[2] = src[2]; dst[3] = src[3];
    }
    __syncthreads();

    // phase 1: S[16][512], warp w covers j in [w*64, w*64+64)
    float accs[8][4] = {};
    {
        const u32* qr0 = sq + gid * QSTR;
        const u32* qr1 = sq + (gid + 8) * QSTR;
        const u32* kbase = g_k2 + (size_t)b * TT * 256 + (size_t)(w * 64 + gid) * 256 + tig * 4;
        #pragma unroll 4
        for (int ks = 0; ks < 16; ks++) {
            uint4 A0 = *(const uint4*)(qr0 + ks * 16 + tig * 4);  // a0h,a2h,a0l,a2l
            uint4 A1 = *(const uint4*)(qr1 + ks * 16 + tig * 4);  // a1h,a3h,a1l,a3l
            #pragma unroll
            for (int nt = 0; nt < 8; nt++) {
                uint4 B = *(const uint4*)(kbase + (size_t)nt * 8 * 256 + ks * 16); // bh0,bh1,bl0,bl1
                mma16816(accs[nt][0],accs[nt][1],accs[nt][2],accs[nt][3],
                         A0.x, A1.x, A0.y, A1.y, B.x, B.y);
                mma16816(accs[nt][0],accs[nt][1],accs[nt][2],accs[nt][3],
                         A0.x, A1.x, A0.y, A1.y, B.z, B.w);
                mma16816(accs[nt][0],accs[nt][1],accs[nt][2],accs[nt][3],
                         A0.z, A1.z, A0.w, A1.w, B.x, B.y);
            }
        }
        #pragma unroll
        for (int nt = 0; nt < 8; nt++) {
            int col = w * 64 + nt * 8 + 2 * tig;
            *(float2*)&ssc[gid * SSTR + col]       = make_float2(accs[nt][0] * SCALE, accs[nt][1] * SCALE);
            *(float2*)&ssc[(gid + 8) * SSTR + col] = make_float2(accs[nt][2] * SCALE, accs[nt][3] * SCALE);
        }
    }
    __syncthreads();

    // softmax: warp w handles rows 2w, 2w+1
    #pragma unroll
    for (int rr = 0; rr < 2; rr++) {
        int rrow = w * 2 + rr;
        float sv[16];
        float mx = -3.4e38f;
        #pragma unroll
        for (int q = 0; q < 16; q++) {
            sv[q] = ssc[rrow * SSTR + q * 32 + lane];
            mx = fmaxf(mx, sv[q]);
        }
        #pragma unroll
        for (int o = 16; o; o >>= 1) mx = fmaxf(mx, __shfl_xor_sync(0xffffffffu, mx, o));
        float sum = 0.f;
        #pragma unroll
        for (int q = 0; q < 16; q++) { sv[q] = __expf(sv[q] - mx); sum += sv[q]; }
        #pragma unroll
        for (int o = 16; o; o >>= 1) sum += __shfl_xor_sync(0xffffffffu, sum, o);
        float inv = 1.f / sum;
        #pragma unroll
        for (int q = 0; q < 16; q++) {
            float p = sv[q] * inv;
            float pr = __shfl_xor_sync(0xffffffffu, p, 1);
            if (!(lane & 1)) {
                u32 ph = cvt2bf(pr, p);
                u32 pl = cvt2bf(pr - bf_hi_f(ph), p - bf_lo_f(ph));
                int jp = q * 16 + (lane >> 1);
                sph[rrow * PSTR + jp] = ph;
                spl[rrow * PSTR + jp] = pl;
            }
        }
    }
    __syncthreads();

    // phase 2: O[16][256], warp w covers d in [w*32, w*32+32)
    float acco[4][4] = {};
    {
        const u32* vbase = g_vt2 + ((size_t)b * 32 * 256 + (size_t)(w * 32 + gid)) * 16 + tig * 4;
        #pragma unroll 4
        for (int ks = 0; ks < 32; ks++) {
            int c0 = ks * 8 + tig;
            u32 a0h = sph[gid * PSTR + c0],       a1h = sph[(gid + 8) * PSTR + c0];
            u32 a2h = sph[gid * PSTR + c0 + 4],   a3h = sph[(gid + 8) * PSTR + c0 + 4];
            u32 a0l = spl[gid * PSTR + c0],       a1l = spl[(gid + 8) * PSTR + c0];
            u32 a2l = spl[gid * PSTR + c0 + 4],   a3l = spl[(gid + 8) * PSTR + c0 + 4];
            #pragma unroll
            for (int nt = 0; nt < 4; nt++) {
                uint4 B = *(const uint4*)(vbase + ((size_t)ks * 256 + nt * 8) * 16);
                mma16816(acco[nt][0],acco[nt][1],acco[nt][2],acco[nt][3],
                         a0h, a1h, a2h, a3h, B.x, B.y);
                mma16816(acco[nt][0],acco[nt][1],acco[nt][2],acco[nt][3],
                         a0h, a1h, a2h, a3h, B.z, B.w);
                mma16816(acco[nt][0],acco[nt][1],acco[nt][2],acco[nt][3],
                         a0l, a1l, a2l, a3l, B.x, B.y);
            }
        }
    }
    #pragma unroll
    for (int nt = 0; nt < 4; nt++) {
        int col = w * 32 + nt * 8 + 2 * tig;
        *(float2*)&out[(size_t)(b * TT + i0 + gid) * CC + col]     = make_float2(acco[nt][0], acco[nt][1]);
        *(float2*)&out[(size_t)(b * TT + i0 + gid + 8) * CC + col] = make_float2(acco[nt][2], acco[nt][3]);
    }
}

// ---------------- launch ----------------
extern "C" void kernel_launch(void* const* d_in, const int* in_sizes, int n_in,
                              void* d_out, int out_size)
{
    (void)in_sizes; (void)n_in; (void)out_size;
    const float* x    = (const float*)d_in[0];
    const float* r    = (const float*)d_in[1];
    const float* w1   = (const float*)d_in[2];
    const float* b1   = (const float*)d_in[3];
    const float* g1   = (const float*)d_in[4];
    const float* be1  = (const float*)d_in[5];
    const float* m1   = (const float*)d_in[6];
    const float* v1   = (const float*)d_in[7];
    const float* w2   = (const float*)d_in[8];
    const float* b2   = (const float*)d_in[9];
    const float* g2   = (const float*)d_in[10];
    const float* be2  = (const float*)d_in[11];
    const float* m2   = (const float*)d_in[12];
    const float* v2   = (const float*)d_in[13];
    const float* wqkv = (const float*)d_in[14];
    float* out = (float*)d_out;

    cudaFuncSetAttribute(attn_kernel, cudaFuncAttributeMaxDynamicSharedMemorySize, ATT_SMEM);

    fold_kernel<<<1, 256>>>(w1, b1, g1, be1, m1, v1, w2, b2, g2, be2, m2, v2);
    bias_kernel<<<BB * TT, 256>>>(x, r);
    qkv_kernel<<<dim3(NQKV / 64, (BB * TT) / 64), 256>>>(wqkv);
    convert_qk_kernel<<<BB * TT / 2, 256>>>();
    convert_v_kernel<<<BB * 32, 256>>>();
    attn_kernel<<<BB * 32, 256, ATT_SMEM>>>(out);
}

// round 9
// speedup vs baseline: 3.8403x; 1.2088x over previous
#include <cuda_runtime.h>
#include <cuda_fp16.h>
#include <cstdint>
#include <cstddef>

typedef unsigned long long u64;
typedef unsigned int u32;

#define TT    512
#define BB    2
#define CC    256
#define TPR   12
#define HID   32
#define INNER 256
#define NQKV  768
#define BN_EPS 1e-5f
#define SCALE  0.0625f

// ---------------- scratch (no allocs allowed) ----------------
__device__ __align__(16) u64   g_w1p[16 * TPR];
__device__ __align__(16) u64   g_b1p[16];
__device__ __align__(16) u32   g_w2ph[16 * CC];   // fp16x2 {k=2kp (lo half), 2kp+1 (hi half)} per [kp][c]
__device__ __align__(16) float g_b2f[CC];
__device__ __align__(16) float g_xb[BB * TT * CC];
__device__ __align__(16) float g_qkv[BB * TT * NQKV];
// q: [row][ks(16)][tig(4)][{h(p), h(p+4), l(p), l(p+4)}] fp16x2, p=ks*8+tig, d=2p,2p+1
__device__ __align__(16) u32   g_q2[BB * TT * 256];
// k: hi-only: [row][ks(16)][tig(4)][{h(p), h(p+4)}]
__device__ __align__(16) u32   g_k2[BB * TT * 128];
// v: hi-only transposed: [b][ks(32)][d(256)][tig(4)][{h(j 2tig,2tig+1), h(2tig+8,+9)}]
__device__ __align__(16) u32   g_vt2[BB * 32 * 256 * 8];

// ---------------- helpers ----------------
__device__ __forceinline__ u64 pk2(float x, float y) {
    u64 r; asm("mov.b64 %0, {%1,%2};" : "=l"(r) : "f"(x), "f"(y)); return r;
}
__device__ __forceinline__ void upk2(u64 v, float &x, float &y) {
    asm("mov.b64 {%0,%1}, %2;" : "=f"(x), "=f"(y) : "l"(v));
}
__device__ __forceinline__ u64 fma2(u64 a, u64 b, u64 c) {
    u64 d; asm("fma.rn.f32x2 %0, %1, %2, %3;" : "=l"(d) : "l"(a), "l"(b), "l"(c)); return d;
}
// fp16x2 pack: lo -> bits[15:0], hi -> bits[31:16]
__device__ __forceinline__ u32 h2pk(float lo, float hi) {
    __half2 t = __floats2half2_rn(lo, hi);
    return *(u32*)&t;
}
__device__ __forceinline__ float2 h2f2(u32 w) {
    __half2 t = *(__half2*)&w;
    return __half22float2(t);
}
__device__ __forceinline__ u32 s2u(const void* p) {
    u32 a; asm("{ .reg .u64 t; cvta.to.shared.u64 t, %1; cvt.u32.u64 %0, t; }" : "=r"(a) : "l"(p));
    return a;
}
__device__ __forceinline__ void mma16816h(float &d0, float &d1, float &d2, float &d3,
                                          u32 a0, u32 a1, u32 a2, u32 a3,
                                          u32 b0, u32 b1) {
    asm volatile("mma.sync.aligned.m16n8k16.row.col.f32.f16.f16.f32 "
                 "{%0,%1,%2,%3}, {%4,%5,%6,%7}, {%8,%9}, {%0,%1,%2,%3};"
                 : "+f"(d0), "+f"(d1), "+f"(d2), "+f"(d3)
                 : "r"(a0), "r"(a1), "r"(a2), "r"(a3), "r"(b0), "r"(b1));
}
__device__ __forceinline__ void ldsm4(u32 &r0, u32 &r1, u32 &r2, u32 &r3, u32 addr) {
    asm volatile("ldmatrix.sync.aligned.m8n8.x4.shared.b16 {%0,%1,%2,%3}, [%4];"
                 : "=r"(r0), "=r"(r1), "=r"(r2), "=r"(r3) : "r"(addr));
}

// ---------------- BN fold + weight packing ----------------
__global__ void fold_kernel(const float* __restrict__ w1, const float* __restrict__ b1,
                            const float* __restrict__ g1, const float* __restrict__ be1,
                            const float* __restrict__ m1, const float* __restrict__ v1,
                            const float* __restrict__ w2, const float* __restrict__ b2,
                            const float* __restrict__ g2, const float* __restrict__ be2,
                            const float* __restrict__ m2, const float* __restrict__ v2)
{
    __shared__ float a1s[HID], b1s[HID];
    int t = threadIdx.x;
    if (t < HID) {
        float a = g1[t] * rsqrtf(v1[t] + BN_EPS);
        a1s[t] = a;
        b1s[t] = (b1[t] - m1[t]) * a + be1[t];
    }
    __syncthreads();
    if (t < 16) {
        for (int d = 0; d < TPR; d++)
            g_w1p[t * TPR + d] = pk2(w1[d * HID + 2 * t]     * a1s[2 * t],
                                     w1[d * HID + 2 * t + 1] * a1s[2 * t + 1]);
        g_b1p[t] = pk2(b1s[2 * t], b1s[2 * t + 1]);
    }
    int c = t;
    float a2 = g2[c] * rsqrtf(v2[c] + BN_EPS);
    g_b2f[c] = (b2[c] - m2[c]) * a2 + be2[c];
    for (int kp = 0; kp < 16; kp++) {
        float w0  = w2[(2 * kp)     * CC + c] * a2;
        float w1v = w2[(2 * kp + 1) * CC + c] * a2;
        g_w2ph[kp * CC + c] = h2pk(w0, w1v);
    }
}

// ---------------- TPR-MLP: fp16 2-term split + ldmatrix + pipelined ----------------
#define H1S 144
#define BIAS_SMEM (2 * 256 * H1S + 208 * 8)

__device__ __forceinline__ void layer1_kp(char* buf, int tid, int kp,
                                          const u64* rp, const u64* w1s)
{
    u64 acc = w1s[192 + kp];
    #pragma unroll
    for (int d = 0; d < 12; d++) acc = fma2(rp[d], w1s[kp * TPR + d], acc);
    float h0, h1; upk2(acc, h0, h1);
    h0 = fmaxf(h0, 0.f); h1 = fmaxf(h1, 0.f);
    u32 hh = h2pk(h0, h1);
    float2 bk = h2f2(hh);
    u32 hl = h2pk(h0 - bk.x, h1 - bk.y);
    u32* row = (u32*)(buf + tid * H1S);
    row[kp]      = hh;
    row[16 + kp] = hl;
}

__global__ __launch_bounds__(256, 2) void bias_kernel(const float* __restrict__ x,
                                                      const float* __restrict__ r)
{
    extern __shared__ char smem[];
    char* buf0 = smem;
    char* buf1 = smem + 256 * H1S;
    u64*  w1s  = (u64*)(smem + 2 * 256 * H1S);

    int tid  = threadIdx.x;
    int bi   = blockIdx.x;
    int warp = tid >> 5, lane = tid & 31;
    int gid  = lane >> 2, tig = lane & 3;

    if (tid < 208) w1s[tid] = (tid < 192) ? g_w1p[tid] : g_b1p[tid - 192];

    // B fragments (fp16 hi-only)
    u32 bh[4][2][2];
    #pragma unroll
    for (int nt = 0; nt < 4; nt++) {
        int c = warp * 32 + nt * 8 + gid;
        #pragma unroll
        for (int ks = 0; ks < 2; ks++) {
            bh[nt][ks][0] = g_w2ph[(ks * 8 + tig)     * CC + c];
            bh[nt][ks][1] = g_w2ph[(ks * 8 + tig + 4) * CC + c];
        }
    }

    // prefetch both r rows for this thread
    const float4* rr0 = (const float4*)(r + (size_t)bi * (TT * TPR) + (size_t)tid * TPR);
    const float4* rr1 = rr0 + 768;   // +256 rows
    float4 A0 = rr0[0], B0 = rr0[1], C0 = rr0[2];
    float4 A1 = rr1[0], B1 = rr1[1], C1 = rr1[2];

    // ldmatrix lane address offset
    int t4 = lane >> 3;
    u32 laneoff = (u32)(((t4 & 1) * 8 + (lane & 7)) * H1S + (t4 >> 1) * 16);
    u32 h1b0 = s2u(buf0) + laneoff;
    u32 h1b1 = s2u(buf1) + laneoff;

    float m0[4], m1[4];
    #pragma unroll
    for (int nt = 0; nt < 4; nt++) { m0[nt] = -3.4e38f; m1[nt] = -3.4e38f; }

    __syncthreads();   // w1s ready

    u64 rp[12];
    rp[0]=pk2(A0.x,A0.x); rp[1]=pk2(A0.y,A0.y); rp[2]=pk2(A0.z,A0.z); rp[3]=pk2(A0.w,A0.w);
    rp[4]=pk2(B0.x,B0.x); rp[5]=pk2(B0.y,B0.y); rp[6]=pk2(B0.z,B0.z); rp[7]=pk2(B0.w,B0.w);
    rp[8]=pk2(C0.x,C0.x); rp[9]=pk2(C0.y,C0.y); rp[10]=pk2(C0.z,C0.z); rp[11]=pk2(C0.w,C0.w);

    #pragma unroll 4
    for (int kp = 0; kp < 16; kp++) layer1_kp(buf0, tid, kp, rp, w1s);

    // repack for chunk 1
    rp[0]=pk2(A1.x,A1.x); rp[1]=pk2(A1.y,A1.y); rp[2]=pk2(A1.z,A1.z); rp[3]=pk2(A1.w,A1.w);
    rp[4]=pk2(B1.x,B1.x); rp[5]=pk2(B1.y,B1.y); rp[6]=pk2(B1.z,B1.z); rp[7]=pk2(B1.w,B1.w);
    rp[8]=pk2(C1.x,C1.x); rp[9]=pk2(C1.y,C1.y); rp[10]=pk2(C1.z,C1.z); rp[11]=pk2(C1.w,C1.w);

    __syncthreads();   // buf0 complete

    // fused: layer-2 chunk0 (tensor pipe) + layer-1 chunk1 (fma pipe)
    #pragma unroll 2
    for (int jt = 0; jt < 16; jt++) {
        u32 a = h1b0 + (u32)jt * (16 * H1S);
        u32 ah0[4], ah1[4], al0[4], al1[4];
        ldsm4(ah0[0],ah0[1],ah0[2],ah0[3], a);
        ldsm4(ah1[0],ah1[1],ah1[2],ah1[3], a + 32);
        ldsm4(al0[0],al0[1],al0[2],al0[3], a + 64);
        ldsm4(al1[0],al1[1],al1[2],al1[3], a + 96);
        #pragma unroll
        for (int nt = 0; nt < 4; nt++) {
            float d0 = 0.f, d1 = 0.f, d2 = 0.f, d3 = 0.f;
            mma16816h(d0,d1,d2,d3, ah0[0],ah0[1],ah0[2],ah0[3], bh[nt][0][0], bh[nt][0][1]);
            mma16816h(d0,d1,d2,d3, ah1[0],ah1[1],ah1[2],ah1[3], bh[nt][1][0], bh[nt][1][1]);
            mma16816h(d0,d1,d2,d3, al0[0],al0[1],al0[2],al0[3], bh[nt][0][0], bh[nt][0][1]);
            mma16816h(d0,d1,d2,d3, al1[0],al1[1],al1[2],al1[3], bh[nt][1][0], bh[nt][1][1]);
            m0[nt] = fmaxf(m0[nt], fmaxf(d0, d2));
            m1[nt] = fmaxf(m1[nt], fmaxf(d1, d3));
        }
        layer1_kp(buf1, tid, jt, rp, w1s);
    }
    __syncthreads();   // buf1 complete

    #pragma unroll 2
    for (int jt = 0; jt < 16; jt++) {
        u32 a = h1b1 + (u32)jt * (16 * H1S);
        u32 ah0[4], ah1[4], al0[4], al1[4];
        ldsm4(ah0[0],ah0[1],ah0[2],ah0[3], a);
        ldsm4(ah1[0],ah1[1],ah1[2],ah1[3], a + 32);
        ldsm4(al0[0],al0[1],al0[2],al0[3], a + 64);
        ldsm4(al1[0],al1[1],al1[2],al1[3], a + 96);
        #pragma unroll
        for (int nt = 0; nt < 4; nt++) {
            float d0 = 0.f, d1 = 0.f, d2 = 0.f, d3 = 0.f;
            mma16816h(d0,d1,d2,d3, ah0[0],ah0[1],ah0[2],ah0[3], bh[nt][0][0], bh[nt][0][1]);
            mma16816h(d0,d1,d2,d3, ah1[0],ah1[1],ah1[2],ah1[3], bh[nt][1][0], bh[nt][1][1]);
            mma16816h(d0,d1,d2,d3, al0[0],al0[1],al0[2],al0[3], bh[nt][0][0], bh[nt][0][1]);
            mma16816h(d0,d1,d2,d3, al1[0],al1[1],al1[2],al1[3], bh[nt][1][0], bh[nt][1][1]);
            m0[nt] = fmaxf(m0[nt], fmaxf(d0, d2));
            m1[nt] = fmaxf(m1[nt], fmaxf(d1, d3));
        }
    }

    #pragma unroll
    for (int nt = 0; nt < 4; nt++) {
        #pragma unroll
        for (int o = 4; o < 32; o <<= 1) {
            m0[nt] = fmaxf(m0[nt], __shfl_xor_sync(0xffffffffu, m0[nt], o));
            m1[nt] = fmaxf(m1[nt], __shfl_xor_sync(0xffffffffu, m1[nt], o));
        }
        if (gid == 0) {
            int c0 = warp * 32 + nt * 8 + tig * 2;
            float b0v = fmaxf(m0[nt] + g_b2f[c0],     0.f);
            float b1v = fmaxf(m1[nt] + g_b2f[c0 + 1], 0.f);
            size_t o0 = (size_t)bi * CC + c0;
            g_xb[o0]     = x[o0]     + b0v;
            g_xb[o0 + 1] = x[o0 + 1] + b1v;
        }
    }
}

// ---------------- qkv = xb @ w_qkv (fp32 SGEMM) ----------------
__global__ __launch_bounds__(256) void qkv_kernel(const float* __restrict__ wqkv)
{
    __shared__ float As[64 * 17];
    __shared__ float Bs[16 * 68];
    int tid = threadIdx.x;
    int tx = tid & 15, ty = tid >> 4;
    int m0 = blockIdx.y * 64, n0 = blockIdx.x * 64;

    float acc[4][4] = {};

    for (int kt = 0; kt < CC; kt += 16) {
        __syncthreads();
        {
            int row = tid >> 2, kc = tid & 3;
            float4 v = *(const float4*)&g_xb[(size_t)(m0 + row) * CC + kt + kc * 4];
            As[row * 17 + kc * 4 + 0] = v.x; As[row * 17 + kc * 4 + 1] = v.y;
            As[row * 17 + kc * 4 + 2] = v.z; As[row * 17 + kc * 4 + 3] = v.w;
        }
        {
            int rr = tid >> 4, cc2 = tid & 15;
            float4 v = *(const float4*)&wqkv[(size_t)(kt + rr) * NQKV + n0 + cc2 * 4];
            *(float4*)&Bs[rr * 68 + cc2 * 4] = v;
        }
        __syncthreads();
        #pragma unroll
        for (int kk = 0; kk < 16; kk++) {
            float a0 = As[(ty * 4 + 0) * 17 + kk];
            float a1 = As[(ty * 4 + 1) * 17 + kk];
            float a2 = As[(ty * 4 + 2) * 17 + kk];
            float a3 = As[(ty * 4 + 3) * 17 + kk];
            float4 bv = *(const float4*)&Bs[kk * 68 + tx * 4];
            acc[0][0] = fmaf(a0, bv.x, acc[0][0]); acc[0][1] = fmaf(a0, bv.y, acc[0][1]);
            acc[0][2] = fmaf(a0, bv.z, acc[0][2]); acc[0][3] = fmaf(a0, bv.w, acc[0][3]);
            acc[1][0] = fmaf(a1, bv.x, acc[1][0]); acc[1][1] = fmaf(a1, bv.y, acc[1][1]);
            acc[1][2] = fmaf(a1, bv.z, acc[1][2]); acc[1][3] = fmaf(a1, bv.w, acc[1][3]);
            acc[2][0] = fmaf(a2, bv.x, acc[2][0]); acc[2][1] = fmaf(a2, bv.y, acc[2][1]);
            acc[2][2] = fmaf(a2, bv.z, acc[2][2]); acc[2][3] = fmaf(a2, bv.w, acc[2][3]);
            acc[3][0] = fmaf(a3, bv.x, acc[3][0]); acc[3][1] = fmaf(a3, bv.y, acc[3][1]);
            acc[3][2] = fmaf(a3, bv.z, acc[3][2]); acc[3][3] = fmaf(a3, bv.w, acc[3][3]);
        }
    }
    #pragma unroll
    for (int m = 0; m < 4; m++) {
        float4 v = make_float4(acc[m][0], acc[m][1], acc[m][2], acc[m][3]);
        *(float4*)&g_qkv[(size_t)(m0 + ty * 4 + m) * NQKV + n0 + tx * 4] = v;
    }
}

// ---------------- convert q (2-term) / k (hi-only) to fp16 fragments ----------------
__global__ __launch_bounds__(256) void convert_qk_kernel()
{
    int tid = threadIdx.x;
    int row  = blockIdx.x * 2 + (tid >> 7);
    int isk  = (tid >> 6) & 1;
    int sub  = tid & 63;
    int p = (sub >> 2) * 8 + (sub & 3);
    const float* src = g_qkv + (size_t)row * NQKV + isk * 256;
    float2 fa = *(const float2*)(src + 2 * p);
    float2 fb = *(const float2*)(src + 2 * p + 8);
    u32 h0 = h2pk(fa.x, fa.y);
    u32 h1 = h2pk(fb.x, fb.y);
    if (isk) {
        *(uint2*)(g_k2 + (size_t)row * 128 + sub * 2) = make_uint2(h0, h1);
    } else {
        float2 r0 = h2f2(h0), r1 = h2f2(h1);
        u32 l0 = h2pk(fa.x - r0.x, fa.y - r0.y);
        u32 l1 = h2pk(fb.x - r1.x, fb.y - r1.y);
        *(uint4*)(g_q2 + (size_t)row * 256 + sub * 4) = make_uint4(h0, h1, l0, l1);
    }
}

// ---------------- convert+transpose V (hi-only) ----------------
__global__ __launch_bounds__(256) void convert_v_kernel()
{
    __shared__ float sv[16 * 256];
    int tid = threadIdx.x;
    int b = blockIdx.x >> 5, ks = blockIdx.x & 31;
    #pragma unroll
    for (int rr = 0; rr < 16; rr++)
        sv[rr * 256 + tid] = g_qkv[(size_t)(b * TT + ks * 16 + rr) * NQKV + 2 * 256 + tid];
    __syncthreads();
    int d = tid;
    u32* dst = g_vt2 + ((size_t)(b * 32 + ks) * 256 + d) * 8;
    #pragma unroll
    for (int tig = 0; tig < 4; tig++) {
        float e0 = sv[(2 * tig)     * 256 + d], o0 = sv[(2 * tig + 1) * 256 + d];
        float e1 = sv[(2 * tig + 8) * 256 + d], o1 = sv[(2 * tig + 9) * 256 + d];
        *(uint2*)(dst + tig * 2) = make_uint2(h2pk(e0, o0), h2pk(e1, o1));
    }
}

// ---------------- fused attention ----------------
#define QSTR 260
#define SSTR 520
#define PSTR 260
#define ATT_SMEM (16*QSTR*4 + 16*SSTR*4 + 2*16*PSTR*4)

__global__ __launch_bounds__(256, 1) void attn_kernel(float* __restrict__ out)
{
    extern __shared__ char smem[];
    u32*   sq  = (u32*)smem;
    float* ssc = (float*)(smem + 16 * QSTR * 4);
    u32*   sph = (u32*)(smem + 16 * QSTR * 4 + 16 * SSTR * 4);
    u32*   spl = sph + 16 * PSTR;

    int tid = threadIdx.x;
    int w = tid >> 5, lane = tid & 31, gid = lane >> 2, tig = lane & 3;
    int b  = blockIdx.x >> 5;
    int i0 = (blockIdx.x & 31) * 16;

    {
        int i = tid >> 4, c0 = (tid & 15) * 16;
        const uint4* src = (const uint4*)(g_q2 + (size_t)(b * TT + i0 + i) * 256 + c0);
        uint4* dst = (uint4*)(sq + i * QSTR + c0);
        dst[0] = src[0]; dst[1] = src[1]; dst[2] = src[2]; dst[3] = src[3];
    }
    __syncthreads();

    // phase 1: S = QK^T, warp w covers j in [w*64, w*64+64)
    float accs[8][4] = {};
    {
        const u32* qr0 = sq + gid * QSTR;
        const u32* qr1 = sq + (gid + 8) * QSTR;
        const u32* kbase = g_k2 + (size_t)(b * TT + w * 64 + gid) * 128 + tig * 2;
        #pragma unroll 4
        for (int ks = 0; ks < 16; ks++) {
            uint4 A0 = *(const uint4*)(qr0 + ks * 16 + tig * 4);
            uint4 A1 = *(const uint4*)(qr1 + ks * 16 + tig * 4);
            #pragma unroll
            for (int nt = 0; nt < 8; nt++) {
                uint2 B = *(const uint2*)(kbase + (size_t)nt * 8 * 128 + ks * 8);
                mma16816h(accs[nt][0],accs[nt][1],accs[nt][2],accs[nt][3],
                          A0.x, A1.x, A0.y, A1.y, B.x, B.y);
                mma16816h(accs[nt][0],accs[nt][1],accs[nt][2],accs[nt][3],
                          A0.z, A1.z, A0.w, A1.w, B.x, B.y);
            }
        }
        #pragma unroll
        for (int nt = 0; nt < 8; nt++) {
            int col = w * 64 + nt * 8 + 2 * tig;
            *(float2*)&ssc[gid * SSTR + col]       = make_float2(accs[nt][0] * SCALE, accs[nt][1] * SCALE);
            *(float2*)&ssc[(gid + 8) * SSTR + col] = make_float2(accs[nt][2] * SCALE, accs[nt][3] * SCALE);
        }
    }
    __syncthreads();

    // softmax: warp w handles rows 2w, 2w+1
    #pragma unroll
    for (int rr = 0; rr < 2; rr++) {
        int rrow = w * 2 + rr;
        float sv[16];
        float mx = -3.4e38f;
        #pragma unroll
        for (int q = 0; q < 16; q++) {
            sv[q] = ssc[rrow * SSTR + q * 32 + lane];
            mx = fmaxf(mx, sv[q]);
        }
        #pragma unroll
        for (int o = 16; o; o >>= 1) mx = fmaxf(mx, __shfl_xor_sync(0xffffffffu, mx, o));
        float sum = 0.f;
        #pragma unroll
        for (int q = 0; q < 16; q++) { sv[q] = __expf(sv[q] - mx); sum += sv[q]; }
        #pragma unroll
        for (int o = 16; o; o >>= 1) sum += __shfl_xor_sync(0xffffffffu, sum, o);
        float inv = 1.f / sum;
        #pragma unroll
        for (int q = 0; q < 16; q++) {
            float p = sv[q] * inv;
            float pr = __shfl_xor_sync(0xffffffffu, p, 1);
            if (!(lane & 1)) {
                u32 ph = h2pk(p, pr);
                float2 bk = h2f2(ph);
                u32 pl = h2pk(p - bk.x, pr - bk.y);
                int jp = q * 16 + (lane >> 1);
                sph[rrow * PSTR + jp] = ph;
                spl[rrow * PSTR + jp] = pl;
            }
        }
    }
    __syncthreads();

    // phase 2: O = P V, warp w covers d in [w*32, w*32+32)
    float acco[4][4] = {};
    {
        const u32* vbase = g_vt2 + ((size_t)b * 32 * 256 + (size_t)(w * 32 + gid)) * 8 + tig * 2;
        #pragma unroll 4
        for (int ks = 0; ks < 32; ks++) {
            int c0 = ks * 8 + tig;
            u32 a0h = sph[gid * PSTR + c0],       a1h = sph[(gid + 8) * PSTR + c0];
            u32 a2h = sph[gid * PSTR + c0 + 4],   a3h = sph[(gid + 8) * PSTR + c0 + 4];
            u32 a0l = spl[gid * PSTR + c0],       a1l = spl[(gid + 8) * PSTR + c0];
            u32 a2l = spl[gid * PSTR + c0 + 4],   a3l = spl[(gid + 8) * PSTR + c0 + 4];
            #pragma unroll
            for (int nt = 0; nt < 4; nt++) {
                uint2 B = *(const uint2*)(vbase + ((size_t)ks * 256 + nt * 8) * 8);
                mma16816h(acco[nt][0],acco[nt][1],acco[nt][2],acco[nt][3],
                          a0h, a1h, a2h, a3h, B.x, B.y);
                mma16816h(acco[nt][0],acco[nt][1],acco[nt][2],acco[nt][3],
                          a0l, a1l, a2l, a3l, B.x, B.y);
            }
        }
    }
    #pragma unroll
    for (int nt = 0; nt < 4; nt++) {
        int col = w * 32 + nt * 8 + 2 * tig;
        *(float2*)&out[(size_t)(b * TT + i0 + gid) * CC + col]     = make_float2(acco[nt][0], acco[nt][1]);
        *(float2*)&out[(size_t)(b * TT + i0 + gid + 8) * CC + col] = make_float2(acco[nt][2], acco[nt][3]);
    }
}

// ---------------- launch ----------------
extern "C" void kernel_launch(void* const* d_in, const int* in_sizes, int n_in,
                              void* d_out, int out_size)
{
    (void)in_sizes; (void)n_in; (void)out_size;
    const float* x    = (const float*)d_in[0];
    const float* r    = (const float*)d_in[1];
    const float* w1   = (const float*)d_in[2];
    const float* b1   = (const float*)d_in[3];
    const float* g1   = (const float*)d_in[4];
    const float* be1  = (const float*)d_in[5];
    const float* m1   = (const float*)d_in[6];
    const float* v1   = (const float*)d_in[7];
    const float* w2   = (const float*)d_in[8];
    const float* b2   = (const float*)d_in[9];
    const float* g2   = (const float*)d_in[10];
    const float* be2  = (const float*)d_in[11];
    const float* m2   = (const float*)d_in[12];
    const float* v2   = (const float*)d_in[13];
    const float* wqkv = (const float*)d_in[14];
    float* out = (float*)d_out;

    cudaFuncSetAttribute(bias_kernel, cudaFuncAttributeMaxDynamicSharedMemorySize, BIAS_SMEM);
    cudaFuncSetAttribute(attn_kernel, cudaFuncAttributeMaxDynamicSharedMemorySize, ATT_SMEM);

    fold_kernel<<<1, 256>>>(w1, b1, g1, be1, m1, v1, w2, b2, g2, be2, m2, v2);
    bias_kernel<<<BB * TT, 256, BIAS_SMEM>>>(x, r);
    qkv_kernel<<<dim3(NQKV / 64, (BB * TT) / 64), 256>>>(wqkv);
    convert_qk_kernel<<<BB * TT / 2, 256>>>();
    convert_v_kernel<<<BB * 32, 256>>>();
    attn_kernel<<<BB * 32, 256, ATT_SMEM>>>(out);
}

// round 11
// speedup vs baseline: 4.3079x; 1.1218x over previous
#include <cuda_runtime.h>
#include <cuda_fp16.h>
#include <cstdint>
#include <cstddef>

typedef unsigned long long u64;
typedef unsigned int u32;

#define TT    512
#define BB    2
#define CC    256
#define TPR   12
#define HID   32
#define INNER 256
#define NQKV  768
#define BN_EPS 1e-5f
#define SCALE  0.0625f

// ---------------- scratch (no allocs allowed) ----------------
__device__ __align__(16) u64   g_w1p[16 * TPR];
__device__ __align__(16) u64   g_b1p[16];
__device__ __align__(16) u32   g_w2ph[16 * CC];   // fp16x2 layer-2 weights
__device__ __align__(16) float g_b2f[CC];
// xb as fp16 hi/lo A-fragment words: [row][ks(16)][tig(4)][half(2)]
__device__ __align__(16) u32   g_xbh[BB * TT * 128];
__device__ __align__(16) u32   g_xbl[BB * TT * 128];
// w_qkv fragment-native: per (n, ks): 4 tig groups of uint4 {bh(p), bh(p+4), bl(p), bl(p+4)}
__device__ __align__(16) u32   g_wq2[NQKV * 16 * 16];
// q: [row][ks(16)][tig(4)][{h(p), h(p+4), l(p), l(p+4)}]
__device__ __align__(16) u32   g_q2[BB * TT * 256];
// k: hi-only: [row][ks(16)][tig(4)][{h(p), h(p+4)}]
__device__ __align__(16) u32   g_k2[BB * TT * 128];
// v transposed hi-only: [b][ksj(32)][d(256)][tigj(4)][{h(j 2tigj,2tigj+1), h(+8,+9)}]
__device__ __align__(16) u32   g_vt2[BB * 32 * 256 * 8];

// ---------------- helpers ----------------
__device__ __forceinline__ u64 pk2(float x, float y) {
    u64 r; asm("mov.b64 %0, {%1,%2};" : "=l"(r) : "f"(x), "f"(y)); return r;
}
__device__ __forceinline__ void upk2(u64 v, float &x, float &y) {
    asm("mov.b64 {%0,%1}, %2;" : "=f"(x), "=f"(y) : "l"(v));
}
__device__ __forceinline__ u64 fma2(u64 a, u64 b, u64 c) {
    u64 d; asm("fma.rn.f32x2 %0, %1, %2, %3;" : "=l"(d) : "l"(a), "l"(b), "l"(c)); return d;
}
__device__ __forceinline__ u32 h2pk(float lo, float hi) {
    __half2 t = __floats2half2_rn(lo, hi);
    return *(u32*)&t;
}
__device__ __forceinline__ float2 h2f2(u32 w) {
    __half2 t = *(__half2*)&w;
    return __half22float2(t);
}
__device__ __forceinline__ u32 s2u(const void* p) {
    u32 a; asm("{ .reg .u64 t; cvta.to.shared.u64 t, %1; cvt.u32.u64 %0, t; }" : "=r"(a) : "l"(p));
    return a;
}
__device__ __forceinline__ void mma16816h(float &d0, float &d1, float &d2, float &d3,
                                          u32 a0, u32 a1, u32 a2, u32 a3,
                                          u32 b0, u32 b1) {
    asm volatile("mma.sync.aligned.m16n8k16.row.col.f32.f16.f16.f32 "
                 "{%0,%1,%2,%3}, {%4,%5,%6,%7}, {%8,%9}, {%0,%1,%2,%3};"
                 : "+f"(d0), "+f"(d1), "+f"(d2), "+f"(d3)
                 : "r"(a0), "r"(a1), "r"(a2), "r"(a3), "r"(b0), "r"(b1));
}
__device__ __forceinline__ void ldsm4(u32 &r0, u32 &r1, u32 &r2, u32 &r3, u32 addr) {
    asm volatile("ldmatrix.sync.aligned.m8n8.x4.shared.b16 {%0,%1,%2,%3}, [%4];"
                 : "=r"(r0), "=r"(r1), "=r"(r2), "=r"(r3) : "r"(addr));
}

// ---------------- BN fold + weight packing ----------------
__global__ void fold_kernel(const float* __restrict__ w1, const float* __restrict__ b1,
                            const float* __restrict__ g1, const float* __restrict__ be1,
                            const float* __restrict__ m1, const float* __restrict__ v1,
                            const float* __restrict__ w2, const float* __restrict__ b2,
                            const float* __restrict__ g2, const float* __restrict__ be2,
                            const float* __restrict__ m2, const float* __restrict__ v2)
{
    __shared__ float a1s[HID], b1s[HID];
    int t = threadIdx.x;
    if (t < HID) {
        float a = g1[t] * rsqrtf(v1[t] + BN_EPS);
        a1s[t] = a;
        b1s[t] = (b1[t] - m1[t]) * a + be1[t];
    }
    __syncthreads();
    if (t < 16) {
        for (int d = 0; d < TPR; d++)
            g_w1p[t * TPR + d] = pk2(w1[d * HID + 2 * t]     * a1s[2 * t],
                                     w1[d * HID + 2 * t + 1] * a1s[2 * t + 1]);
        g_b1p[t] = pk2(b1s[2 * t], b1s[2 * t + 1]);
    }
    int c = t;
    float a2 = g2[c] * rsqrtf(v2[c] + BN_EPS);
    g_b2f[c] = (b2[c] - m2[c]) * a2 + be2[c];
    for (int kp = 0; kp < 16; kp++) {
        float w0  = w2[(2 * kp)     * CC + c] * a2;
        float w1v = w2[(2 * kp + 1) * CC + c] * a2;
        g_w2ph[kp * CC + c] = h2pk(w0, w1v);
    }
}

// ---------------- w_qkv -> fragment-native fp16 hi/lo ----------------
// grid (3, 64), block 256: n = bx*256+tx; ks = by>>2; tig = by&3
__global__ __launch_bounds__(256) void convert_w_kernel(const float* __restrict__ wqkv)
{
    int n = blockIdx.x * 256 + threadIdx.x;
    int ks = blockIdx.y >> 2, tig = blockIdx.y & 3;
    int k0 = (ks * 8 + tig) * 2;
    float w0 = wqkv[(size_t)k0 * NQKV + n];
    float w1 = wqkv[(size_t)(k0 + 1) * NQKV + n];
    float w8 = wqkv[(size_t)(k0 + 8) * NQKV + n];
    float w9 = wqkv[(size_t)(k0 + 9) * NQKV + n];
    u32 bh0 = h2pk(w0, w1), bh1 = h2pk(w8, w9);
    float2 r0 = h2f2(bh0), r1 = h2f2(bh1);
    u32 bl0 = h2pk(w0 - r0.x, w1 - r0.y);
    u32 bl1 = h2pk(w8 - r1.x, w9 - r1.y);
    *(uint4*)(g_wq2 + ((size_t)(n * 16 + ks) * 4 + tig) * 4) = make_uint4(bh0, bh1, bl0, bl1);
}

// ---------------- TPR-MLP: fp16 2-term split + ldmatrix + pipelined ----------------
#define H1S 144
#define BIAS_SMEM (2 * 256 * H1S + 208 * 8)

__device__ __forceinline__ void layer1_kp(char* buf, int tid, int kp,
                                          const u64* rp, const u64* w1s)
{
    u64 acc = w1s[192 + kp];
    #pragma unroll
    for (int d = 0; d < 12; d++) acc = fma2(rp[d], w1s[kp * TPR + d], acc);
    float h0, h1; upk2(acc, h0, h1);
    h0 = fmaxf(h0, 0.f); h1 = fmaxf(h1, 0.f);
    u32 hh = h2pk(h0, h1);
    float2 bk = h2f2(hh);
    u32 hl = h2pk(h0 - bk.x, h1 - bk.y);
    u32* row = (u32*)(buf + tid * H1S);
    row[kp]      = hh;
    row[16 + kp] = hl;
}

__global__ __launch_bounds__(256, 2) void bias_kernel(const float* __restrict__ x,
                                                      const float* __restrict__ r)
{
    extern __shared__ char smem[];
    char* buf0 = smem;
    char* buf1 = smem + 256 * H1S;
    u64*  w1s  = (u64*)(smem + 2 * 256 * H1S);

    int tid  = threadIdx.x;
    int bi   = blockIdx.x;
    int warp = tid >> 5, lane = tid & 31;
    int gid  = lane >> 2, tig = lane & 3;

    if (tid < 208) w1s[tid] = (tid < 192) ? g_w1p[tid] : g_b1p[tid - 192];

    u32 bh[4][2][2];
    #pragma unroll
    for (int nt = 0; nt < 4; nt++) {
        int c = warp * 32 + nt * 8 + gid;
        #pragma unroll
        for (int ks = 0; ks < 2; ks++) {
            bh[nt][ks][0] = g_w2ph[(ks * 8 + tig)     * CC + c];
            bh[nt][ks][1] = g_w2ph[(ks * 8 + tig + 4) * CC + c];
        }
    }

    const float4* rr0 = (const float4*)(r + (size_t)bi * (TT * TPR) + (size_t)tid * TPR);
    const float4* rr1 = rr0 + 768;
    float4 A0 = rr0[0], B0 = rr0[1], C0 = rr0[2];
    float4 A1 = rr1[0], B1 = rr1[1], C1 = rr1[2];

    int t4 = lane >> 3;
    u32 laneoff = (u32)(((t4 & 1) * 8 + (lane & 7)) * H1S + (t4 >> 1) * 16);
    u32 h1b0 = s2u(buf0) + laneoff;
    u32 h1b1 = s2u(buf1) + laneoff;

    float m0[4], m1[4];
    #pragma unroll
    for (int nt = 0; nt < 4; nt++) { m0[nt] = -3.4e38f; m1[nt] = -3.4e38f; }

    __syncthreads();

    u64 rp[12];
    rp[0]=pk2(A0.x,A0.x); rp[1]=pk2(A0.y,A0.y); rp[2]=pk2(A0.z,A0.z); rp[3]=pk2(A0.w,A0.w);
    rp[4]=pk2(B0.x,B0.x); rp[5]=pk2(B0.y,B0.y); rp[6]=pk2(B0.z,B0.z); rp[7]=pk2(B0.w,B0.w);
    rp[8]=pk2(C0.x,C0.x); rp[9]=pk2(C0.y,C0.y); rp[10]=pk2(C0.z,C0.z); rp[11]=pk2(C0.w,C0.w);

    #pragma unroll 4
    for (int kp = 0; kp < 16; kp++) layer1_kp(buf0, tid, kp, rp, w1s);

    rp[0]=pk2(A1.x,A1.x); rp[1]=pk2(A1.y,A1.y); rp[2]=pk2(A1.z,A1.z); rp[3]=pk2(A1.w,A1.w);
    rp[4]=pk2(B1.x,B1.x); rp[5]=pk2(B1.y,B1.y); rp[6]=pk2(B1.z,B1.z); rp[7]=pk2(B1.w,B1.w);
    rp[8]=pk2(C1.x,C1.x); rp[9]=pk2(C1.y,C1.y); rp[10]=pk2(C1.z,C1.z); rp[11]=pk2(C1.w,C1.w);

    __syncthreads();

    #pragma unroll 2
    for (int jt = 0; jt < 16; jt++) {
        u32 a = h1b0 + (u32)jt * (16 * H1S);
        u32 ah0[4], ah1[4], al0[4], al1[4];
        ldsm4(ah0[0],ah0[1],ah0[2],ah0[3], a);
        ldsm4(ah1[0],ah1[1],ah1[2],ah1[3], a + 32);
        ldsm4(al0[0],al0[1],al0[2],al0[3], a + 64);
        ldsm4(al1[0],al1[1],al1[2],al1[3], a + 96);
        #pragma unroll
        for (int nt = 0; nt < 4; nt++) {
            float d0 = 0.f, d1 = 0.f, d2 = 0.f, d3 = 0.f;
            mma16816h(d0,d1,d2,d3, ah0[0],ah0[1],ah0[2],ah0[3], bh[nt][0][0], bh[nt][0][1]);
            mma16816h(d0,d1,d2,d3, ah1[0],ah1[1],ah1[2],ah1[3], bh[nt][1][0], bh[nt][1][1]);
            mma16816h(d0,d1,d2,d3, al0[0],al0[1],al0[2],al0[3], bh[nt][0][0], bh[nt][0][1]);
            mma16816h(d0,d1,d2,d3, al1[0],al1[1],al1[2],al1[3], bh[nt][1][0], bh[nt][1][1]);
            m0[nt] = fmaxf(m0[nt], fmaxf(d0, d2));
            m1[nt] = fmaxf(m1[nt], fmaxf(d1, d3));
        }
        layer1_kp(buf1, tid, jt, rp, w1s);
    }
    __syncthreads();

    #pragma unroll 2
    for (int jt = 0; jt < 16; jt++) {
        u32 a = h1b1 + (u32)jt * (16 * H1S);
        u32 ah0[4], ah1[4], al0[4], al1[4];
        ldsm4(ah0[0],ah0[1],ah0[2],ah0[3], a);
        ldsm4(ah1[0],ah1[1],ah1[2],ah1[3], a + 32);
        ldsm4(al0[0],al0[1],al0[2],al0[3], a + 64);
        ldsm4(al1[0],al1[1],al1[2],al1[3], a + 96);
        #pragma unroll
        for (int nt = 0; nt < 4; nt++) {
            float d0 = 0.f, d1 = 0.f, d2 = 0.f, d3 = 0.f;
            mma16816h(d0,d1,d2,d3, ah0[0],ah0[1],ah0[2],ah0[3], bh[nt][0][0], bh[nt][0][1]);
            mma16816h(d0,d1,d2,d3, ah1[0],ah1[1],ah1[2],ah1[3], bh[nt][1][0], bh[nt][1][1]);
            mma16816h(d0,d1,d2,d3, al0[0],al0[1],al0[2],al0[3], bh[nt][0][0], bh[nt][0][1]);
            mma16816h(d0,d1,d2,d3, al1[0],al1[1],al1[2],al1[3], bh[nt][1][0], bh[nt][1][1]);
            m0[nt] = fmaxf(m0[nt], fmaxf(d0, d2));
            m1[nt] = fmaxf(m1[nt], fmaxf(d1, d3));
        }
    }

    #pragma unroll
    for (int nt = 0; nt < 4; nt++) {
        #pragma unroll
        for (int o = 4; o < 32; o <<= 1) {
            m0[nt] = fmaxf(m0[nt], __shfl_xor_sync(0xffffffffu, m0[nt], o));
            m1[nt] = fmaxf(m1[nt], __shfl_xor_sync(0xffffffffu, m1[nt], o));
        }
        if (gid == 0) {
            int c0 = warp * 32 + nt * 8 + tig * 2;
            float v0 = x[(size_t)bi * CC + c0]     + fmaxf(m0[nt] + g_b2f[c0],     0.f);
            float v1 = x[(size_t)bi * CC + c0 + 1] + fmaxf(m1[nt] + g_b2f[c0 + 1], 0.f);
            int P = c0 >> 1;
            int word = (P & ~7) + ((P & 3) << 1) + ((P >> 2) & 1);
            u32 hi = h2pk(v0, v1);
            float2 bk = h2f2(hi);
            g_xbh[bi * 128 + word] = hi;
            g_xbl[bi * 128 + word] = h2pk(v0 - bk.x, v1 - bk.y);
        }
    }
}

// ---------------- qkv via fp16 MMA (3-term), epilogue writes fragment layouts ----
// grid (12, 16), block 128 (4 warps x 16 rows). blockIdx.x: 0-3 q, 4-7 k, 8-11 v.
__global__ __launch_bounds__(128) void qkv_mma_kernel()
{
    int tid = threadIdx.x;
    int warp = tid >> 5, lane = tid & 31, gid = lane >> 2, tig = lane & 3;
    int r0 = blockIdx.y * 64 + warp * 16;
    int n0 = blockIdx.x * 64;
    int type = blockIdx.x >> 2;

    const u32* ah = g_xbh + (size_t)(r0 + gid) * 128 + tig * 2;
    const u32* al = g_xbl + (size_t)(r0 + gid) * 128 + tig * 2;

    float acc[8][4] = {};
    #pragma unroll 4
    for (int ks = 0; ks < 16; ks++) {
        uint2 Ah0 = *(const uint2*)(ah + ks * 8);
        uint2 Ah1 = *(const uint2*)(ah + 8 * 128 + ks * 8);
        uint2 Al0 = *(const uint2*)(al + ks * 8);
        uint2 Al1 = *(const uint2*)(al + 8 * 128 + ks * 8);
        #pragma unroll
        for (int nt = 0; nt < 8; nt++) {
            int n = n0 + nt * 8 + gid;
            uint4 B = *(const uint4*)(g_wq2 + ((size_t)(n * 16 + ks) * 4 + tig) * 4);
            mma16816h(acc[nt][0],acc[nt][1],acc[nt][2],acc[nt][3],
                      Ah0.x, Ah1.x, Ah0.y, Ah1.y, B.x, B.y);
            mma16816h(acc[nt][0],acc[nt][1],acc[nt][2],acc[nt][3],
                      Ah0.x, Ah1.x, Ah0.y, Ah1.y, B.z, B.w);
            mma16816h(acc[nt][0],acc[nt][1],acc[nt][2],acc[nt][3],
                      Al0.x, Al1.x, Al0.y, Al1.y, B.x, B.y);
        }
    }

    if (type == 0) {
        // q: 2-term fp16 fragment words
        #pragma unroll
        for (int nt = 0; nt < 8; nt++) {
            int P = (n0 >> 1) + nt * 4 + tig;
            int word = ((P >> 3) << 4) + ((P & 3) << 2) + ((P >> 2) & 1);
            u32* q0 = g_q2 + (size_t)(r0 + gid) * 256 + word;
            u32* q1 = g_q2 + (size_t)(r0 + gid + 8) * 256 + word;
            u32 h0 = h2pk(acc[nt][0], acc[nt][1]); float2 b0 = h2f2(h0);
            u32 h1 = h2pk(acc[nt][2], acc[nt][3]); float2 b1 = h2f2(h1);
            q0[0] = h0; q0[2] = h2pk(acc[nt][0] - b0.x, acc[nt][1] - b0.y);
            q1[0] = h1; q1[2] = h2pk(acc[nt][2] - b1.x, acc[nt][3] - b1.y);
        }
    } else if (type == 1) {
        // k: hi-only
        #pragma unroll
        for (int nt = 0; nt < 8; nt++) {
            int P = ((n0 - 256) >> 1) + nt * 4 + tig;
            int word = (P & ~7) + ((P & 3) << 1) + ((P >> 2) & 1);
            g_k2[(size_t)(r0 + gid) * 128 + word]     = h2pk(acc[nt][0], acc[nt][1]);
            g_k2[(size_t)(r0 + gid + 8) * 128 + word] = h2pk(acc[nt][2], acc[nt][3]);
        }
    } else {
        // v: transpose via shfl, hi-only
        int bb = r0 >> 9, ksj = (r0 & 511) >> 4;
        #pragma unroll
        for (int nt = 0; nt < 8; nt++) {
            float p0 = __shfl_xor_sync(0xffffffffu, acc[nt][0], 4);
            float p1 = __shfl_xor_sync(0xffffffffu, acc[nt][1], 4);
            float p2 = __shfl_xor_sync(0xffffffffu, acc[nt][2], 4);
            float p3 = __shfl_xor_sync(0xffffffffu, acc[nt][3], 4);
            if (!(gid & 1)) {
                int tigj = gid >> 1;
                int d0c = n0 - 512 + nt * 8 + 2 * tig;
                u32* v0p = g_vt2 + ((size_t)(bb * 32 + ksj) * 256 + d0c) * 8 + tigj * 2;
                v0p[0] = h2pk(acc[nt][0], p0);
                v0p[1] = h2pk(acc[nt][2], p2);
                u32* v1p = v0p + 8;
                v1p[0] = h2pk(acc[nt][1], p1);
                v1p[1] = h2pk(acc[nt][3], p3);
            }
        }
    }
}

// ---------------- fused attention ----------------
#define QSTR 260
#define SSTR 520
#define PSTR 260
#define ATT_SMEM (16*QSTR*4 + 16*SSTR*4 + 2*16*PSTR*4)

__global__ __launch_bounds__(256, 1) void attn_kernel(float* __restrict__ out)
{
    extern __shared__ char smem[];
    u32*   sq  = (u32*)smem;
    float* ssc = (float*)(smem + 16 * QSTR * 4);
    u32*   sph = (u32*)(smem + 16 * QSTR * 4 + 16 * SSTR * 4);
    u32*   spl = sph + 16 * PSTR;

    int tid = threadIdx.x;
    int w = tid >> 5, lane = tid & 31, gid = lane >> 2, tig = lane & 3;
    int b  = blockIdx.x >> 5;
    int i0 = (blockIdx.x & 31) * 16;

    {
        int i = tid >> 4, c0 = (tid & 15) * 16;
        const uint4* src = (const uint4*)(g_q2 + (size_t)(b * TT + i0 + i) * 256 + c0);
        uint4* dst = (uint4*)(sq + i * QSTR + c0);
        dst[0] = src[0]; dst[1] = src[1]; dst[2] = src[2]; dst[3] = src[3];
    }
    __syncthreads();

    float accs[8][4] = {};
    {
        const u32* qr0 = sq + gid * QSTR;
        const u32* qr1 = sq + (gid + 8) * QSTR;
        const u32* kbase = g_k2 + (size_t)(b * TT + w * 64 + gid) * 128 + tig * 2;
        #pragma unroll 4
        for (int ks = 0; ks < 16; ks++) {
            uint4 A0 = *(const uint4*)(qr0 + ks * 16 + tig * 4);
            uint4 A1 = *(const uint4*)(qr1 + ks * 16 + tig * 4);
            #pragma unroll
            for (int nt = 0; nt < 8; nt++) {
                uint2 B = *(const uint2*)(kbase + (size_t)nt * 8 * 128 + ks * 8);
                mma16816h(accs[nt][0],accs[nt][1],accs[nt][2],accs[nt][3],
                          A0.x, A1.x, A0.y, A1.y, B.x, B.y);
                mma16816h(accs[nt][0],accs[nt][1],accs[nt][2],accs[nt][3],
                          A0.z, A1.z, A0.w, A1.w, B.x, B.y);
            }
        }
        #pragma unroll
        for (int nt = 0; nt < 8; nt++) {
            int col = w * 64 + nt * 8 + 2 * tig;
            *(float2*)&ssc[gid * SSTR + col]       = make_float2(accs[nt][0] * SCALE, accs[nt][1] * SCALE);
            *(float2*)&ssc[(gid + 8) * SSTR + col] = make_float2(accs[nt][2] * SCALE, accs[nt][3] * SCALE);
        }
    }
    __syncthreads();

    #pragma unroll
    for (int rr = 0; rr < 2; rr++) {
        int rrow = w * 2 + rr;
        float sv[16];
        float mx = -3.4e38f;
        #pragma unroll
        for (int q = 0; q < 16; q++) {
            sv[q] = ssc[rrow * SSTR + q * 32 + lane];
            mx = fmaxf(mx, sv[q]);
        }
        #pragma unroll
        for (int o = 16; o; o >>= 1) mx = fmaxf(mx, __shfl_xor_sync(0xffffffffu, mx, o));
        float sum = 0.f;
        #pragma unroll
        for (int q = 0; q < 16; q++) { sv[q] = __expf(sv[q] - mx); sum += sv[q]; }
        #pragma unroll
        for (int o = 16; o; o >>= 1) sum += __shfl_xor_sync(0xffffffffu, sum, o);
        float inv = 1.f / sum;
        #pragma unroll
        for (int q = 0; q < 16; q++) {
            float p = sv[q] * inv;
            float pr = __shfl_xor_sync(0xffffffffu, p, 1);
            if (!(lane & 1)) {
                u32 ph = h2pk(p, pr);
                float2 bk = h2f2(ph);
                u32 pl = h2pk(p - bk.x, pr - bk.y);
                int jp = q * 16 + (lane >> 1);
                sph[rrow * PSTR + jp] = ph;
                spl[rrow * PSTR + jp] = pl;
            }
        }
    }
    __syncthreads();

    float acco[4][4] = {};
    {
        const u32* vbase = g_vt2 + ((size_t)b * 32 * 256 + (size_t)(w * 32 + gid)) * 8 + tig * 2;
        #pragma unroll 4
        for (int ks = 0; ks < 32; ks++) {
            int c0 = ks * 8 + tig;
            u32 a0h = sph[gid * PSTR + c0],       a1h = sph[(gid + 8) * PSTR + c0];
            u32 a2h = sph[gid * PSTR + c0 + 4],   a3h = sph[(gid + 8) * PSTR + c0 + 4];
            u32 a0l = spl[gid * PSTR + c0],       a1l = spl[(gid + 8) * PSTR + c0];
            u32 a2l = spl[gid * PSTR + c0 + 4],   a3l = spl[(gid + 8) * PSTR + c0 + 4];
            #pragma unroll
            for (int nt = 0; nt < 4; nt++) {
                uint2 B = *(const uint2*)(vbase + ((size_t)ks * 256 + nt * 8) * 8);
                mma16816h(acco[nt][0],acco[nt][1],acco[nt][2],acco[nt][3],
                          a0h, a1h, a2h, a3h, B.x, B.y);
                mma16816h(acco[nt][0],acco[nt][1],acco[nt][2],acco[nt][3],
                          a0l, a1l, a2l, a3l, B.x, B.y);
            }
        }
    }
    #pragma unroll
    for (int nt = 0; nt < 4; nt++) {
        int col = w * 32 + nt * 8 + 2 * tig;
        *(float2*)&out[(size_t)(b * TT + i0 + gid) * CC + col]     = make_float2(acco[nt][0], acco[nt][1]);
        *(float2*)&out[(size_t)(b * TT + i0 + gid + 8) * CC + col] = make_float2(acco[nt][2], acco[nt][3]);
    }
}

// ---------------- launch ----------------
extern "C" void kernel_launch(void* const* d_in, const int* in_sizes, int n_in,
                              void* d_out, int out_size)
{
    (void)in_sizes; (void)n_in; (void)out_size;
    const float* x    = (const float*)d_in[0];
    const float* r    = (const float*)d_in[1];
    const float* w1   = (const float*)d_in[2];
    const float* b1   = (const float*)d_in[3];
    const float* g1   = (const float*)d_in[4];
    const float* be1  = (const float*)d_in[5];
    const float* m1   = (const float*)d_in[6];
    const float* v1   = (const float*)d_in[7];
    const float* w2   = (const float*)d_in[8];
    const float* b2   = (const float*)d_in[9];
    const float* g2   = (const float*)d_in[10];
    const float* be2  = (const float*)d_in[11];
    const float* m2   = (const float*)d_in[12];
    const float* v2   = (const float*)d_in[13];
    const float* wqkv = (const float*)d_in[14];
    float* out = (float*)d_out;

    cudaFuncSetAttribute(bias_kernel, cudaFuncAttributeMaxDynamicSharedMemorySize, BIAS_SMEM);
    cudaFuncSetAttribute(attn_kernel, cudaFuncAttributeMaxDynamicSharedMemorySize, ATT_SMEM);

    fold_kernel<<<1, 256>>>(w1, b1, g1, be1, m1, v1, w2, b2, g2, be2, m2, v2);
    convert_w_kernel<<<dim3(3, 64), 256>>>(wqkv);
    bias_kernel<<<BB * TT, 256, BIAS_SMEM>>>(x, r);
    qkv_mma_kernel<<<dim3(12, 16), 128>>>();
    attn_kernel<<<BB * 32, 256, ATT_SMEM>>>(out);
}

// round 13
// speedup vs baseline: 5.3493x; 1.2417x over previous
#include <cuda_runtime.h>
#include <cuda_fp16.h>
#include <cstdint>
#include <cstddef>

typedef unsigned long long u64;
typedef unsigned int u32;

#define TT    512
#define BB    2
#define CC    256
#define TPR   12
#define HID   32
#define INNER 256
#define NQKV  768
#define BN_EPS 1e-5f
#define SCALE  0.0625f

// ---------------- scratch (no allocs allowed) ----------------
__device__ __align__(16) u64   g_w1p[16 * TPR];
__device__ __align__(16) u64   g_b1p[16];
__device__ __align__(16) u32   g_w2ph[16 * CC];   // fp16x2 layer-2 weights
__device__ __align__(16) float g_b2f[CC];
// xb as fp16 hi/lo A-fragment words: [row][ks(16)][tig(4)][half(2)]
__device__ __align__(16) u32   g_xbh[BB * TT * 128];
__device__ __align__(16) u32   g_xbl[BB * TT * 128];
// w_qkv fragment-native: per (n, ks): 4 tig groups of uint4 {bh(p), bh(p+4), bl(p), bl(p+4)}
__device__ __align__(16) u32   g_wq2[NQKV * 16 * 16];
// q: [row][ks(16)][tig(4)][{h(p), h(p+4), l(p), l(p+4)}]
__device__ __align__(16) u32   g_q2[BB * TT * 256];
// k: hi-only: [row][ks(16)][tig(4)][{h(p), h(p+4)}]
__device__ __align__(16) u32   g_k2[BB * TT * 128];
// v transposed hi-only: [b][ksj(32)][d(256)][tigj(4)][{h(j 2tigj,2tigj+1), h(+8,+9)}]
__device__ __align__(16) u32   g_vt2[BB * 32 * 256 * 8];

// ---------------- helpers ----------------
__device__ __forceinline__ u64 pk2(float x, float y) {
    u64 r; asm("mov.b64 %0, {%1,%2};" : "=l"(r) : "f"(x), "f"(y)); return r;
}
__device__ __forceinline__ void upk2(u64 v, float &x, float &y) {
    asm("mov.b64 {%0,%1}, %2;" : "=f"(x), "=f"(y) : "l"(v));
}
__device__ __forceinline__ u64 fma2(u64 a, u64 b, u64 c) {
    u64 d; asm("fma.rn.f32x2 %0, %1, %2, %3;" : "=l"(d) : "l"(a), "l"(b), "l"(c)); return d;
}
__device__ __forceinline__ u32 h2pk(float lo, float hi) {
    __half2 t = __floats2half2_rn(lo, hi);
    return *(u32*)&t;
}
__device__ __forceinline__ float2 h2f2(u32 w) {
    __half2 t = *(__half2*)&w;
    return __half22float2(t);
}
__device__ __forceinline__ u32 s2u(const void* p) {
    u32 a; asm("{ .reg .u64 t; cvta.to.shared.u64 t, %1; cvt.u32.u64 %0, t; }" : "=r"(a) : "l"(p));
    return a;
}
__device__ __forceinline__ void mma16816h(float &d0, float &d1, float &d2, float &d3,
                                          u32 a0, u32 a1, u32 a2, u32 a3,
                                          u32 b0, u32 b1) {
    asm volatile("mma.sync.aligned.m16n8k16.row.col.f32.f16.f16.f32 "
                 "{%0,%1,%2,%3}, {%4,%5,%6,%7}, {%8,%9}, {%0,%1,%2,%3};"
                 : "+f"(d0), "+f"(d1), "+f"(d2), "+f"(d3)
                 : "r"(a0), "r"(a1), "r"(a2), "r"(a3), "r"(b0), "r"(b1));
}
__device__ __forceinline__ void ldsm4(u32 &r0, u32 &r1, u32 &r2, u32 &r3, u32 addr) {
    asm volatile("ldmatrix.sync.aligned.m8n8.x4.shared.b16 {%0,%1,%2,%3}, [%4];"
                 : "=r"(r0), "=r"(r1), "=r"(r2), "=r"(r3) : "r"(addr));
}

// ---------------- prep: fold (block 192) + w_qkv convert (blocks 0-191) ----------------
__global__ void prep_kernel(const float* __restrict__ w1, const float* __restrict__ b1,
                            const float* __restrict__ g1, const float* __restrict__ be1,
                            const float* __restrict__ m1, const float* __restrict__ v1,
                            const float* __restrict__ w2, const float* __restrict__ b2,
                            const float* __restrict__ g2, const float* __restrict__ be2,
                            const float* __restrict__ m2, const float* __restrict__ v2,
                            const float* __restrict__ wqkv)
{
    if (blockIdx.x < 192) {
        int n = (blockIdx.x % 3) * 256 + threadIdx.x;
        int byy = blockIdx.x / 3;
        int ks = byy >> 2, tig = byy & 3;
        int k0 = (ks * 8 + tig) * 2;
        float w0 = wqkv[(size_t)k0 * NQKV + n];
        float w1v = wqkv[(size_t)(k0 + 1) * NQKV + n];
        float w8 = wqkv[(size_t)(k0 + 8) * NQKV + n];
        float w9 = wqkv[(size_t)(k0 + 9) * NQKV + n];
        u32 bh0 = h2pk(w0, w1v), bh1 = h2pk(w8, w9);
        float2 r0 = h2f2(bh0), r1 = h2f2(bh1);
        u32 bl0 = h2pk(w0 - r0.x, w1v - r0.y);
        u32 bl1 = h2pk(w8 - r1.x, w9 - r1.y);
        *(uint4*)(g_wq2 + ((size_t)(n * 16 + ks) * 4 + tig) * 4) = make_uint4(bh0, bh1, bl0, bl1);
        return;
    }
    // fold
    __shared__ float a1s[HID], b1s[HID];
    int t = threadIdx.x;
    if (t < HID) {
        float a = g1[t] * rsqrtf(v1[t] + BN_EPS);
        a1s[t] = a;
        b1s[t] = (b1[t] - m1[t]) * a + be1[t];
    }
    __syncthreads();
    if (t < 16) {
        for (int d = 0; d < TPR; d++)
            g_w1p[t * TPR + d] = pk2(w1[d * HID + 2 * t]     * a1s[2 * t],
                                     w1[d * HID + 2 * t + 1] * a1s[2 * t + 1]);
        g_b1p[t] = pk2(b1s[2 * t], b1s[2 * t + 1]);
    }
    int c = t;
    float a2 = g2[c] * rsqrtf(v2[c] + BN_EPS);
    g_b2f[c] = (b2[c] - m2[c]) * a2 + be2[c];
    for (int kp = 0; kp < 16; kp++) {
        float w0  = w2[(2 * kp)     * CC + c] * a2;
        float w1v = w2[(2 * kp + 1) * CC + c] * a2;
        g_w2ph[kp * CC + c] = h2pk(w0, w1v);
    }
}

// ---------------- TPR-MLP: hi-only fp16 h1 + ldmatrix + pipelined ----------------
#define H1S 80
#define BIAS_SMEM (2 * 256 * H1S + 208 * 8)

__device__ __forceinline__ void layer1_kp(char* buf, int tid, int kp,
                                          const u64* rp, const u64* w1s)
{
    u64 acc = w1s[192 + kp];
    #pragma unroll
    for (int d = 0; d < 12; d++) acc = fma2(rp[d], w1s[kp * TPR + d], acc);
    float h0, h1; upk2(acc, h0, h1);
    h0 = fmaxf(h0, 0.f); h1 = fmaxf(h1, 0.f);
    ((u32*)(buf + tid * H1S))[kp] = h2pk(h0, h1);
}

__global__ __launch_bounds__(256, 2) void bias_kernel(const float* __restrict__ x,
                                                      const float* __restrict__ r)
{
    extern __shared__ char smem[];
    char* buf0 = smem;
    char* buf1 = smem + 256 * H1S;
    u64*  w1s  = (u64*)(smem + 2 * 256 * H1S);

    int tid  = threadIdx.x;
    int bi   = blockIdx.x;
    int warp = tid >> 5, lane = tid & 31;
    int gid  = lane >> 2, tig = lane & 3;

    if (tid < 208) w1s[tid] = (tid < 192) ? g_w1p[tid] : g_b1p[tid - 192];

    u32 bh[4][2][2];
    #pragma unroll
    for (int nt = 0; nt < 4; nt++) {
        int c = warp * 32 + nt * 8 + gid;
        #pragma unroll
        for (int ks = 0; ks < 2; ks++) {
            bh[nt][ks][0] = g_w2ph[(ks * 8 + tig)     * CC + c];
            bh[nt][ks][1] = g_w2ph[(ks * 8 + tig + 4) * CC + c];
        }
    }

    const float4* rr0 = (const float4*)(r + (size_t)bi * (TT * TPR) + (size_t)tid * TPR);
    const float4* rr1 = rr0 + 768;
    float4 A0 = rr0[0], B0 = rr0[1], C0 = rr0[2];
    float4 A1 = rr1[0], B1 = rr1[1], C1 = rr1[2];

    int t4 = lane >> 3;
    u32 laneoff = (u32)(((t4 & 1) * 8 + (lane & 7)) * H1S + (t4 >> 1) * 16);
    u32 h1b0 = s2u(buf0) + laneoff;
    u32 h1b1 = s2u(buf1) + laneoff;

    float m0[4], m1[4];
    #pragma unroll
    for (int nt = 0; nt < 4; nt++) { m0[nt] = -3.4e38f; m1[nt] = -3.4e38f; }

    __syncthreads();

    u64 rp[12];
    rp[0]=pk2(A0.x,A0.x); rp[1]=pk2(A0.y,A0.y); rp[2]=pk2(A0.z,A0.z); rp[3]=pk2(A0.w,A0.w);
    rp[4]=pk2(B0.x,B0.x); rp[5]=pk2(B0.y,B0.y); rp[6]=pk2(B0.z,B0.z); rp[7]=pk2(B0.w,B0.w);
    rp[8]=pk2(C0.x,C0.x); rp[9]=pk2(C0.y,C0.y); rp[10]=pk2(C0.z,C0.z); rp[11]=pk2(C0.w,C0.w);

    #pragma unroll 4
    for (int kp = 0; kp < 16; kp++) layer1_kp(buf0, tid, kp, rp, w1s);

    rp[0]=pk2(A1.x,A1.x); rp[1]=pk2(A1.y,A1.y); rp[2]=pk2(A1.z,A1.z); rp[3]=pk2(A1.w,A1.w);
    rp[4]=pk2(B1.x,B1.x); rp[5]=pk2(B1.y,B1.y); rp[6]=pk2(B1.z,B1.z); rp[7]=pk2(B1.w,B1.w);
    rp[8]=pk2(C1.x,C1.x); rp[9]=pk2(C1.y,C1.y); rp[10]=pk2(C1.z,C1.z); rp[11]=pk2(C1.w,C1.w);

    __syncthreads();

    // fused: layer-2 chunk0 (tensor pipe) + layer-1 chunk1 (fma pipe)
    #pragma unroll 2
    for (int jt = 0; jt < 16; jt++) {
        u32 a = h1b0 + (u32)jt * (16 * H1S);
        u32 ah0[4], ah1[4];
        ldsm4(ah0[0],ah0[1],ah0[2],ah0[3], a);
        ldsm4(ah1[0],ah1[1],ah1[2],ah1[3], a + 32);
        #pragma unroll
        for (int nt = 0; nt < 4; nt++) {
            float d0 = 0.f, d1 = 0.f, d2 = 0.f, d3 = 0.f;
            mma16816h(d0,d1,d2,d3, ah0[0],ah0[1],ah0[2],ah0[3], bh[nt][0][0], bh[nt][0][1]);
            mma16816h(d0,d1,d2,d3, ah1[0],ah1[1],ah1[2],ah1[3], bh[nt][1][0], bh[nt][1][1]);
            m0[nt] = fmaxf(m0[nt], fmaxf(d0, d2));
            m1[nt] = fmaxf(m1[nt], fmaxf(d1, d3));
        }
        layer1_kp(buf1, tid, jt, rp, w1s);
    }
    __syncthreads();

    #pragma unroll 2
    for (int jt = 0; jt < 16; jt++) {
        u32 a = h1b1 + (u32)jt * (16 * H1S);
        u32 ah0[4], ah1[4];
        ldsm4(ah0[0],ah0[1],ah0[2],ah0[3], a);
        ldsm4(ah1[0],ah1[1],ah1[2],ah1[3], a + 32);
        #pragma unroll
        for (int nt = 0; nt < 4; nt++) {
            float d0 = 0.f, d1 = 0.f, d2 = 0.f, d3 = 0.f;
            mma16816h(d0,d1,d2,d3, ah0[0],ah0[1],ah0[2],ah0[3], bh[nt][0][0], bh[nt][0][1]);
            mma16816h(d0,d1,d2,d3, ah1[0],ah1[1],ah1[2],ah1[3], bh[nt][1][0], bh[nt][1][1]);
            m0[nt] = fmaxf(m0[nt], fmaxf(d0, d2));
            m1[nt] = fmaxf(m1[nt], fmaxf(d1, d3));
        }
    }

    #pragma unroll
    for (int nt = 0; nt < 4; nt++) {
        #pragma unroll
        for (int o = 4; o < 32; o <<= 1) {
            m0[nt] = fmaxf(m0[nt], __shfl_xor_sync(0xffffffffu, m0[nt], o));
            m1[nt] = fmaxf(m1[nt], __shfl_xor_sync(0xffffffffu, m1[nt], o));
        }
        if (gid == 0) {
            int c0 = warp * 32 + nt * 8 + tig * 2;
            float v0 = x[(size_t)bi * CC + c0]     + fmaxf(m0[nt] + g_b2f[c0],     0.f);
            float v1 = x[(size_t)bi * CC + c0 + 1] + fmaxf(m1[nt] + g_b2f[c0 + 1], 0.f);
            int P = c0 >> 1;
            int word = (P & ~7) + ((P & 3) << 1) + ((P >> 2) & 1);
            u32 hi = h2pk(v0, v1);
            float2 bk = h2f2(hi);
            g_xbh[bi * 128 + word] = hi;
            g_xbl[bi * 128 + word] = h2pk(v0 - bk.x, v1 - bk.y);
        }
    }
}

// ---------------- qkv via fp16 MMA (3-term), k-split across warp pairs ----------
// grid (12, 16), block 256 (8 warps): warp = (rowtile 0-3, khalf 0-1).
__global__ __launch_bounds__(256) void qkv_mma_kernel()
{
    __shared__ float sacc[4][8][32][4];   // 16 KB partial sums from khalf 0
    int tid = threadIdx.x;
    int warp = tid >> 5, lane = tid & 31, gid = lane >> 2, tig = lane & 3;
    int rt = warp & 3, kh = warp >> 2;
    int r0 = blockIdx.y * 64 + rt * 16;
    int n0 = blockIdx.x * 64;
    int type = blockIdx.x >> 2;

    const u32* ah = g_xbh + (size_t)(r0 + gid) * 128 + kh * 64 + tig * 2;
    const u32* al = g_xbl + (size_t)(r0 + gid) * 128 + kh * 64 + tig * 2;

    float acc[8][4] = {};
    #pragma unroll 4
    for (int ks = 0; ks < 8; ks++) {
        uint2 Ah0 = *(const uint2*)(ah + ks * 8);
        uint2 Ah1 = *(const uint2*)(ah + 8 * 128 + ks * 8);
        uint2 Al0 = *(const uint2*)(al + ks * 8);
        uint2 Al1 = *(const uint2*)(al + 8 * 128 + ks * 8);
        #pragma unroll
        for (int nt = 0; nt < 8; nt++) {
            int n = n0 + nt * 8 + gid;
            uint4 B = *(const uint4*)(g_wq2 + ((size_t)(n * 16 + kh * 8 + ks) * 4 + tig) * 4);
            mma16816h(acc[nt][0],acc[nt][1],acc[nt][2],acc[nt][3],
                      Ah0.x, Ah1.x, Ah0.y, Ah1.y, B.x, B.y);
            mma16816h(acc[nt][0],acc[nt][1],acc[nt][2],acc[nt][3],
                      Ah0.x, Ah1.x, Ah0.y, Ah1.y, B.z, B.w);
            mma16816h(acc[nt][0],acc[nt][1],acc[nt][2],acc[nt][3],
                      Al0.x, Al1.x, Al0.y, Al1.y, B.x, B.y);
        }
    }

    if (kh == 0) {
        #pragma unroll
        for (int nt = 0; nt < 8; nt++)
            *(float4*)&sacc[rt][nt][lane][0] = make_float4(acc[nt][0], acc[nt][1], acc[nt][2], acc[nt][3]);
    }
    __syncthreads();
    if (kh == 0) return;

    #pragma unroll
    for (int nt = 0; nt < 8; nt++) {
        float4 t = *(float4*)&sacc[rt][nt][lane][0];
        acc[nt][0] += t.x; acc[nt][1] += t.y; acc[nt][2] += t.z; acc[nt][3] += t.w;
    }

    if (type == 0) {
        #pragma unroll
        for (int nt = 0; nt < 8; nt++) {
            int P = (n0 >> 1) + nt * 4 + tig;
            int word = ((P >> 3) << 4) + ((P & 3) << 2) + ((P >> 2) & 1);
            u32* q0 = g_q2 + (size_t)(r0 + gid) * 256 + word;
            u32* q1 = g_q2 + (size_t)(r0 + gid + 8) * 256 + word;
            u32 h0 = h2pk(acc[nt][0], acc[nt][1]); float2 b0 = h2f2(h0);
            u32 h1 = h2pk(acc[nt][2], acc[nt][3]); float2 b1 = h2f2(h1);
            q0[0] = h0; q0[2] = h2pk(acc[nt][0] - b0.x, acc[nt][1] - b0.y);
            q1[0] = h1; q1[2] = h2pk(acc[nt][2] - b1.x, acc[nt][3] - b1.y);
        }
    } else if (type == 1) {
        #pragma unroll
        for (int nt = 0; nt < 8; nt++) {
            int P = ((n0 - 256) >> 1) + nt * 4 + tig;
            int word = (P & ~7) + ((P & 3) << 1) + ((P >> 2) & 1);
            g_k2[(size_t)(r0 + gid) * 128 + word]     = h2pk(acc[nt][0], acc[nt][1]);
            g_k2[(size_t)(r0 + gid + 8) * 128 + word] = h2pk(acc[nt][2], acc[nt][3]);
        }
    } else {
        int bb = r0 >> 9, ksj = (r0 & 511) >> 4;
        #pragma unroll
        for (int nt = 0; nt < 8; nt++) {
            float p0 = __shfl_xor_sync(0xffffffffu, acc[nt][0], 4);
            float p1 = __shfl_xor_sync(0xffffffffu, acc[nt][1], 4);
            float p2 = __shfl_xor_sync(0xffffffffu, acc[nt][2], 4);
            float p3 = __shfl_xor_sync(0xffffffffu, acc[nt][3], 4);
            if (!(gid & 1)) {
                int tigj = gid >> 1;
                int d0c = n0 - 512 + nt * 8 + 2 * tig;
                u32* v0p = g_vt2 + ((size_t)(bb * 32 + ksj) * 256 + d0c) * 8 + tigj * 2;
                v0p[0] = h2pk(acc[nt][0], p0);
                v0p[1] = h2pk(acc[nt][2], p2);
                u32* v1p = v0p + 8;
                v1p[0] = h2pk(acc[nt][1], p1);
                v1p[1] = h2pk(acc[nt][3], p3);
            }
        }
    }
}

// ---------------- fused attention ----------------
#define QSTR 260
#define SSTR 520
#define PSTR 260
#define ATT_SMEM (16*QSTR*4 + 16*SSTR*4 + 2*16*PSTR*4)

__global__ __launch_bounds__(256, 1) void attn_kernel(float* __restrict__ out)
{
    extern __shared__ char smem[];
    u32*   sq  = (u32*)smem;
    float* ssc = (float*)(smem + 16 * QSTR * 4);
    u32*   sph = (u32*)(smem + 16 * QSTR * 4 + 16 * SSTR * 4);
    u32*   spl = sph + 16 * PSTR;

    int tid = threadIdx.x;
    int w = tid >> 5, lane = tid & 31, gid = lane >> 2, tig = lane & 3;
    int b  = blockIdx.x >> 5;
    int i0 = (blockIdx.x & 31) * 16;

    {
        int i = tid >> 4, c0 = (tid & 15) * 16;
        const uint4* src = (const uint4*)(g_q2 + (size_t)(b * TT + i0 + i) * 256 + c0);
        uint4* dst = (uint4*)(sq + i * QSTR + c0);
        dst[0] = src[0]; dst[1] = src[1]; dst[2] = src[2]; dst[3] = src[3];
    }
    __syncthreads();

    float accs[8][4] = {};
    {
        const u32* qr0 = sq + gid * QSTR;
        const u32* qr1 = sq + (gid + 8) * QSTR;
        const u32* kbase = g_k2 + (size_t)(b * TT + w * 64 + gid) * 128 + tig * 2;
        #pragma unroll 4
        for (int ks = 0; ks < 16; ks++) {
            uint4 A0 = *(const uint4*)(qr0 + ks * 16 + tig * 4);
            uint4 A1 = *(const uint4*)(qr1 + ks * 16 + tig * 4);
            #pragma unroll
            for (int nt = 0; nt < 8; nt++) {
                uint2 B = *(const uint2*)(kbase + (size_t)nt * 8 * 128 + ks * 8);
                mma16816h(accs[nt][0],accs[nt][1],accs[nt][2],accs[nt][3],
                          A0.x, A1.x, A0.y, A1.y, B.x, B.y);
                mma16816h(accs[nt][0],accs[nt][1],accs[nt][2],accs[nt][3],
                          A0.z, A1.z, A0.w, A1.w, B.x, B.y);
            }
        }
        #pragma unroll
        for (int nt = 0; nt < 8; nt++) {
            int col = w * 64 + nt * 8 + 2 * tig;
            *(float2*)&ssc[gid * SSTR + col]       = make_float2(accs[nt][0] * SCALE, accs[nt][1] * SCALE);
            *(float2*)&ssc[(gid + 8) * SSTR + col] = make_float2(accs[nt][2] * SCALE, accs[nt][3] * SCALE);
        }
    }
    __syncthreads();

    #pragma unroll
    for (int rr = 0; rr < 2; rr++) {
        int rrow = w * 2 + rr;
        float sv[16];
        float mx = -3.4e38f;
        #pragma unroll
        for (int q = 0; q < 16; q++) {
            sv[q] = ssc[rrow * SSTR + q * 32 + lane];
            mx = fmaxf(mx, sv[q]);
        }
        #pragma unroll
        for (int o = 16; o; o >>= 1) mx = fmaxf(mx, __shfl_xor_sync(0xffffffffu, mx, o));
        float sum = 0.f;
        #pragma unroll
        for (int q = 0; q < 16; q++) { sv[q] = __expf(sv[q] - mx); sum += sv[q]; }
        #pragma unroll
        for (int o = 16; o; o >>= 1) sum += __shfl_xor_sync(0xffffffffu, sum, o);
        float inv = 1.f / sum;
        #pragma unroll
        for (int q = 0; q < 16; q++) {
            float p = sv[q] * inv;
            float pr = __shfl_xor_sync(0xffffffffu, p, 1);
            if (!(lane & 1)) {
                u32 ph = h2pk(p, pr);
                float2 bk = h2f2(ph);
                u32 pl = h2pk(p - bk.x, pr - bk.y);
                int jp = q * 16 + (lane >> 1);
                sph[rrow * PSTR + jp] = ph;
                spl[rrow * PSTR + jp] = pl;
            }
        }
    }
    __syncthreads();

    float acco[4][4] = {};
    {
        const u32* vbase = g_vt2 + ((size_t)b * 32 * 256 + (size_t)(w * 32 + gid)) * 8 + tig * 2;
        #pragma unroll 4
        for (int ks = 0; ks < 32; ks++) {
            int c0 = ks * 8 + tig;
            u32 a0h = sph[gid * PSTR + c0],       a1h = sph[(gid + 8) * PSTR + c0];
            u32 a2h = sph[gid * PSTR + c0 + 4],   a3h = sph[(gid + 8) * PSTR + c0 + 4];
            u32 a0l = spl[gid * PSTR + c0],       a1l = spl[(gid + 8) * PSTR + c0];
            u32 a2l = spl[gid * PSTR + c0 + 4],   a3l = spl[(gid + 8) * PSTR + c0 + 4];
            #pragma unroll
            for (int nt = 0; nt < 4; nt++) {
                uint2 B = *(const uint2*)(vbase + ((size_t)ks * 256 + nt * 8) * 8);
                mma16816h(acco[nt][0],acco[nt][1],acco[nt][2],acco[nt][3],
                          a0h, a1h, a2h, a3h, B.x, B.y);
                mma16816h(acco[nt][0],acco[nt][1],acco[nt][2],acco[nt][3],
                          a0l, a1l, a2l, a3l, B.x, B.y);
            }
        }
    }
    #pragma unroll
    for (int nt = 0; nt < 4; nt++) {
        int col = w * 32 + nt * 8 + 2 * tig;
        *(float2*)&out[(size_t)(b * TT + i0 + gid) * CC + col]     = make_float2(acco[nt][0], acco[nt][1]);
        *(float2*)&out[(size_t)(b * TT + i0 + gid + 8) * CC + col] = make_float2(acco[nt][2], acco[nt][3]);
    }
}

// ---------------- launch ----------------
extern "C" void kernel_launch(void* const* d_in, const int* in_sizes, int n_in,
                              void* d_out, int out_size)
{
    (void)in_sizes; (void)n_in; (void)out_size;
    const float* x    = (const float*)d_in[0];
    const float* r    = (const float*)d_in[1];
    const float* w1   = (const float*)d_in[2];
    const float* b1   = (const float*)d_in[3];
    const float* g1   = (const float*)d_in[4];
    const float* be1  = (const float*)d_in[5];
    const float* m1   = (const float*)d_in[6];
    const float* v1   = (const float*)d_in[7];
    const float* w2   = (const float*)d_in[8];
    const float* b2   = (const float*)d_in[9];
    const float* g2   = (const float*)d_in[10];
    const float* be2  = (const float*)d_in[11];
    const float* m2   = (const float*)d_in[12];
    const float* v2   = (const float*)d_in[13];
    const float* wqkv = (const float*)d_in[14];
    float* out = (float*)d_out;

    cudaFuncSetAttribute(bias_kernel, cudaFuncAttributeMaxDynamicSharedMemorySize, BIAS_SMEM);
    cudaFuncSetAttribute(attn_kernel, cudaFuncAttributeMaxDynamicSharedMemorySize, ATT_SMEM);

    prep_kernel<<<193, 256>>>(w1, b1, g1, be1, m1, v1, w2, b2, g2, be2, m2, v2, wqkv);
    bias_kernel<<<BB * TT, 256, BIAS_SMEM>>>(x, r);
    qkv_mma_kernel<<<dim3(12, 16), 256>>>();
    attn_kernel<<<BB * 32, 256, ATT_SMEM>>>(out);
}